// round 1
// baseline (speedup 1.0000x reference)
#include <cuda_runtime.h>
#include <math.h>

#define BATCH 2
#define C0 192
#define HH 192
#define WW 192
#define HW (HH*WW)          // 36864
#define C3 (3*C0)           // 576
#define NH 4
#define HD 48

// ---------------- scratch (device globals; no allocs allowed) --------------
__device__ float g_qkv1[BATCH*C3*HW];      // after 1x1 conv
__device__ float g_qkv2[BATCH*C3*HW];      // after depthwise 3x3
__device__ float g_norm[BATCH*2*C0];       // [b][q|k][c]  L2 norms
__device__ float g_attn[BATCH*NH*HD*HD];   // raw dots -> softmaxed attn
__device__ float g_w2[BATCH*C0*C0];        // w_proj @ blockdiag(attn)

// ---------------- GEMM: C[M,N] = A[M,K] @ B[K,N], row-major ----------------
// BM=64, BN=128, BK=8, 256 threads, 4x8 per-thread tile.
// Requires M%64==0, N%128==0, K%8==0 (true for all uses here).
__global__ void __launch_bounds__(256) gemm64x128(
    const float* __restrict__ A, const float* __restrict__ Bm, float* __restrict__ Cm,
    int K, int lda, int ldb, int ldc, int sA, int sB, int sC)
{
    const int bz = blockIdx.z;
    const float* Ab = A + (size_t)bz * sA;
    const float* Bb = Bm + (size_t)bz * sB;
    float*       Cb = Cm + (size_t)bz * sC;

    const int m0 = blockIdx.y * 64;
    const int n0 = blockIdx.x * 128;

    __shared__ float As[8][64];
    __shared__ float Bs[8][128];

    const int tid = threadIdx.x;
    const int tx = tid & 15;   // n-dir, 8 cols each
    const int ty = tid >> 4;   // m-dir, 4 rows each

    float acc[4][8];
#pragma unroll
    for (int i = 0; i < 4; i++)
#pragma unroll
        for (int j = 0; j < 8; j++) acc[i][j] = 0.f;

    for (int k0 = 0; k0 < K; k0 += 8) {
        // A tile: 64x8 = 512 elems, 2 per thread
#pragma unroll
        for (int r = 0; r < 2; r++) {
            int idx = tid + r * 256;
            int i = idx >> 3, j = idx & 7;
            As[j][i] = Ab[(m0 + i) * lda + k0 + j];
        }
        // B tile: 8x128 = 1024 elems, one float4 per thread
        {
            int j = tid >> 5;          // 0..7
            int p = (tid & 31) * 4;    // 0..124
            float4 v = *reinterpret_cast<const float4*>(&Bb[(size_t)(k0 + j) * ldb + n0 + p]);
            *reinterpret_cast<float4*>(&Bs[j][p]) = v;
        }
        __syncthreads();

#pragma unroll
        for (int kk = 0; kk < 8; kk++) {
            float a[4], b[8];
#pragma unroll
            for (int i = 0; i < 4; i++) a[i] = As[kk][ty * 4 + i];
#pragma unroll
            for (int j = 0; j < 8; j++) b[j] = Bs[kk][tx * 8 + j];
#pragma unroll
            for (int i = 0; i < 4; i++)
#pragma unroll
                for (int j = 0; j < 8; j++) acc[i][j] += a[i] * b[j];
        }
        __syncthreads();
    }

#pragma unroll
    for (int i = 0; i < 4; i++) {
        int row = m0 + ty * 4 + i;
        float4 v0 = make_float4(acc[i][0], acc[i][1], acc[i][2], acc[i][3]);
        float4 v1 = make_float4(acc[i][4], acc[i][5], acc[i][6], acc[i][7]);
        *reinterpret_cast<float4*>(&Cb[(size_t)row * ldc + n0 + tx * 8])     = v0;
        *reinterpret_cast<float4*>(&Cb[(size_t)row * ldc + n0 + tx * 8 + 4]) = v1;
    }
}

// ---------------- depthwise 3x3, SAME padding (cross-correlation) ----------
__global__ void dwconv3x3(const float* __restrict__ in, const float* __restrict__ wdw,
                          float* __restrict__ out)
{
    const int x  = blockIdx.x * 32 + threadIdx.x;
    const int y  = blockIdx.y * 8 + threadIdx.y;
    const int bc = blockIdx.z;           // b*C3 + o
    const int o  = bc % C3;
    const float* ip = in + (size_t)bc * HW;
    const float* wp = wdw + o * 9;

    float s = 0.f;
#pragma unroll
    for (int dy = 0; dy < 3; dy++) {
        int yy = y + dy - 1;
        if (yy < 0 || yy >= HH) continue;
#pragma unroll
        for (int dx = 0; dx < 3; dx++) {
            int xx = x + dx - 1;
            if (xx < 0 || xx >= WW) continue;
            s += ip[yy * WW + xx] * wp[dy * 3 + dx];
        }
    }
    out[(size_t)bc * HW + y * WW + x] = s;
}

// ---------------- per-row L2 norms of q,k over hw --------------------------
__global__ void __launch_bounds__(256) rownorm(const float* __restrict__ qkv2,
                                               float* __restrict__ norm)
{
    const int r = blockIdx.x;            // [0, BATCH*2*C0)
    const int b = r / (2 * C0);
    const int t = (r / C0) % 2;          // 0=q, 1=k
    const int c = r % C0;
    const float* p = qkv2 + ((size_t)b * C3 + t * C0 + c) * HW;

    float s = 0.f;
    for (int i = threadIdx.x; i < HW; i += 256) {
        float v = p[i];
        s += v * v;
    }
    __shared__ float red[256];
    red[threadIdx.x] = s;
    __syncthreads();
    for (int st = 128; st > 0; st >>= 1) {
        if (threadIdx.x < st) red[threadIdx.x] += red[threadIdx.x + st];
        __syncthreads();
    }
    if (threadIdx.x == 0) norm[r] = fmaxf(sqrtf(red[0]), 1e-12f);
}

// ---------------- zero the attn accumulator --------------------------------
__global__ void zero_attn(float* __restrict__ a)
{
    int i = blockIdx.x * 256 + threadIdx.x;
    if (i < BATCH * NH * HD * HD) a[i] = 0.f;
}

// ---------------- split-K q·k^T : 48x48 per (b,h), atomic accumulate -------
#define SPLITS 72
#define CHUNK (HW / SPLITS)   // 512
__global__ void __launch_bounds__(256) attn_qk(const float* __restrict__ qkv2,
                                               float* __restrict__ attn)
{
    const int split = blockIdx.x;
    const int bh = blockIdx.y;            // b*NH + h
    const int b = bh / NH, h = bh % NH;
    const float* qp = qkv2 + ((size_t)b * C3 +        h * HD) * HW;
    const float* kp = qkv2 + ((size_t)b * C3 + C0 +   h * HD) * HW;
    const int n0 = split * CHUNK;

    __shared__ float Qs[48][33];
    __shared__ float Ks[48][33];

    const int tid = threadIdx.x;
    const int tx = tid & 15;   // e-dir, 3 each
    const int ty = tid >> 4;   // d-dir, 3 each

    float acc[3][3] = {};

    for (int nb = 0; nb < CHUNK; nb += 32) {
#pragma unroll
        for (int r = 0; r < 6; r++) {
            int idx = tid + r * 256;
            int d = idx >> 5, nn = idx & 31;
            Qs[d][nn] = qp[(size_t)d * HW + n0 + nb + nn];
            Ks[d][nn] = kp[(size_t)d * HW + n0 + nb + nn];
        }
        __syncthreads();
#pragma unroll
        for (int kk = 0; kk < 32; kk++) {
            float a[3], bb[3];
#pragma unroll
            for (int i = 0; i < 3; i++) a[i]  = Qs[ty * 3 + i][kk];
#pragma unroll
            for (int j = 0; j < 3; j++) bb[j] = Ks[tx * 3 + j][kk];
#pragma unroll
            for (int i = 0; i < 3; i++)
#pragma unroll
                for (int j = 0; j < 3; j++) acc[i][j] += a[i] * bb[j];
        }
        __syncthreads();
    }

    float* ap = attn + (size_t)bh * HD * HD;
#pragma unroll
    for (int i = 0; i < 3; i++)
#pragma unroll
        for (int j = 0; j < 3; j++)
            atomicAdd(&ap[(ty * 3 + i) * HD + tx * 3 + j], acc[i][j]);
}

// ---------------- scale by norms + temperature, softmax over e -------------
__global__ void softmax_attn(float* __restrict__ attn, const float* __restrict__ norm,
                             const float* __restrict__ logtemp)
{
    const int bh = blockIdx.x;
    const int b = bh / NH, h = bh % NH;
    const int d = threadIdx.x;
    if (d >= HD) return;

    float lt = logtemp[h];
    float temp = (lt > 20.f ? lt : log1pf(expf(lt))) + 1e-6f;

    const float* nq = norm + (b * 2 + 0) * C0 + h * HD;
    const float* nk = norm + (b * 2 + 1) * C0 + h * HD;
    float* row = attn + ((size_t)bh * HD + d) * HD;
    const float qn = nq[d];

    float vals[HD];
    float mx = -1e30f;
#pragma unroll
    for (int e = 0; e < HD; e++) {
        float v = row[e] / (qn * nk[e]) * temp;
        vals[e] = v;
        mx = fmaxf(mx, v);
    }
    float s = 0.f;
#pragma unroll
    for (int e = 0; e < HD; e++) {
        vals[e] = expf(vals[e] - mx);
        s += vals[e];
    }
    float inv = 1.f / s;
#pragma unroll
    for (int e = 0; e < HD; e++) row[e] = vals[e] * inv;
}

// ---------------- W2[b] = w_proj @ blockdiag(attn[b]) ----------------------
__global__ void build_w2(const float* __restrict__ wproj, const float* __restrict__ attn,
                         float* __restrict__ w2)
{
    int idx = blockIdx.x * 256 + threadIdx.x;
    if (idx >= BATCH * C0 * C0) return;
    int cc = idx % C0;
    int o  = (idx / C0) % C0;
    int b  = idx / (C0 * C0);
    int h = cc / HD, e = cc % HD;
    float s = 0.f;
#pragma unroll
    for (int d = 0; d < HD; d++)
        s += wproj[o * C0 + h * HD + d] * attn[(((size_t)b * NH + h) * HD + d) * HD + e];
    w2[idx] = s;
}

// ---------------- launcher -------------------------------------------------
extern "C" void kernel_launch(void* const* d_in, const int* in_sizes, int n_in,
                              void* d_out, int out_size)
{
    const float* x      = (const float*)d_in[0];  // [2,192,192,192]
    const float* w_qkv  = (const float*)d_in[1];  // [576,192]
    const float* w_dw   = (const float*)d_in[2];  // [576,1,3,3]
    const float* w_proj = (const float*)d_in[3];  // [192,192]
    const float* ltemp  = (const float*)d_in[4];  // [4,1,1]
    float* out = (float*)d_out;

    float *qkv1, *qkv2, *norm, *attn, *w2;
    cudaGetSymbolAddress((void**)&qkv1, g_qkv1);
    cudaGetSymbolAddress((void**)&qkv2, g_qkv2);
    cudaGetSymbolAddress((void**)&norm, g_norm);
    cudaGetSymbolAddress((void**)&attn, g_attn);
    cudaGetSymbolAddress((void**)&w2,   g_w2);

    // 1) qkv1 = w_qkv @ x  : M=576, K=192, N=36864, batch=2
    {
        dim3 grid(HW / 128, C3 / 64, BATCH);
        gemm64x128<<<grid, 256>>>(w_qkv, x, qkv1,
                                  C0, C0, HW, HW,
                                  0, C0 * HW, C3 * HW);
    }
    // 2) depthwise 3x3
    {
        dim3 grid(WW / 32, HH / 8, BATCH * C3);
        dwconv3x3<<<grid, dim3(32, 8)>>>(qkv1, w_dw, qkv2);
    }
    // 3) L2 norms of q,k rows
    rownorm<<<BATCH * 2 * C0, 256>>>(qkv2, norm);
    // 4) zero attn accumulator, then split-K q.k^T
    zero_attn<<<(BATCH * NH * HD * HD + 255) / 256, 256>>>(attn);
    {
        dim3 grid(SPLITS, BATCH * NH);
        attn_qk<<<grid, 256>>>(qkv2, attn);
    }
    // 5) softmax (with norm division + temperature)
    softmax_attn<<<BATCH * NH, 64>>>(attn, norm, ltemp);
    // 6) W2 = w_proj @ blockdiag(attn)
    build_w2<<<(BATCH * C0 * C0 + 255) / 256, 256>>>(w_proj, attn, w2);
    // 7) out = W2 @ v  : M=192, K=192, N=36864, batch=2  (v = qkv2 channels [384,576))
    {
        dim3 grid(HW / 128, C0 / 64, BATCH);
        gemm64x128<<<grid, 256>>>(w2, qkv2 + (size_t)2 * C0 * HW, out,
                                  C0, C0, HW, HW,
                                  C0 * C0, C3 * HW, C0 * HW);
    }
}

// round 3
// speedup vs baseline: 1.9488x; 1.9488x over previous
#include <cuda_runtime.h>
#include <cuda_bf16.h>
#include <math.h>
#include <cstdint>

#define BATCH 2
#define C0 192
#define HH 192
#define WW 192
#define HW (HH*WW)          // 36864
#define C3 (3*C0)           // 576
#define NH 4
#define HD 48
#define KDIM 192

typedef __nv_bfloat16 bf16;

// ---------------- scratch (device globals; no allocs allowed) --------------
__device__ float g_qkv1[BATCH*C3*HW];      // after 1x1 conv
__device__ float g_qkv2[BATCH*C3*HW];      // after depthwise 3x3
__device__ float g_norm[BATCH*2*C0];       // [b][q|k][c]  L2 norms
__device__ float g_attn[BATCH*NH*HD*HD];   // raw dots -> softmaxed attn
__device__ bf16  g_xh[BATCH*C0*HW];        // x hi plane
__device__ bf16  g_xl[BATCH*C0*HW];        // x lo plane
__device__ bf16  g_vh[BATCH*C0*HW];        // v hi plane
__device__ bf16  g_vl[BATCH*C0*HW];        // v lo plane
__device__ bf16  g_wqh[C3*C0];             // w_qkv hi
__device__ bf16  g_wql[C3*C0];             // w_qkv lo
__device__ bf16  g_w2h[BATCH*C0*C0];       // w2 hi
__device__ bf16  g_w2l[BATCH*C0*C0];       // w2 lo

// ======================= small helpers =====================================
__device__ __forceinline__ uint32_t smem_u32(const void* p) {
    uint32_t a;
    asm("{ .reg .u64 t; cvta.to.shared.u64 t, %1; cvt.u32.u64 %0, t; }"
        : "=r"(a) : "l"(p));
    return a;
}
__device__ __forceinline__ void ldsm4(uint32_t addr, uint32_t* r) {
    asm volatile("ldmatrix.sync.aligned.m8n8.x4.shared.b16 {%0,%1,%2,%3}, [%4];"
        : "=r"(r[0]), "=r"(r[1]), "=r"(r[2]), "=r"(r[3]) : "r"(addr));
}
__device__ __forceinline__ void ldsm4t(uint32_t addr, uint32_t* r) {
    asm volatile("ldmatrix.sync.aligned.m8n8.x4.trans.shared.b16 {%0,%1,%2,%3}, [%4];"
        : "=r"(r[0]), "=r"(r[1]), "=r"(r[2]), "=r"(r[3]) : "r"(addr));
}
__device__ __forceinline__ void mma16816(float* d, const uint32_t* a, const uint32_t* b) {
    asm volatile(
        "mma.sync.aligned.m16n8k16.row.col.f32.bf16.bf16.f32 "
        "{%0,%1,%2,%3}, {%4,%5,%6,%7}, {%8,%9}, {%0,%1,%2,%3};"
        : "+f"(d[0]), "+f"(d[1]), "+f"(d[2]), "+f"(d[3])
        : "r"(a[0]), "r"(a[1]), "r"(a[2]), "r"(a[3]), "r"(b[0]), "r"(b[1]));
}
__device__ __forceinline__ void cpa16(uint32_t dst, const void* src, int bytes) {
    asm volatile("cp.async.cg.shared.global [%0], [%1], 16, %2;"
        :: "r"(dst), "l"(src), "r"(bytes));
}
#define CP_COMMIT() asm volatile("cp.async.commit_group;")
#define CP_WAIT(n)  asm volatile("cp.async.wait_group %0;" :: "n"(n))

// ======================= split-bf16 conversion =============================
// out planes are [b][per_batch] contiguous; src has batch stride bstride.
__global__ void __launch_bounds__(256) split_batched(
    const float* __restrict__ src, size_t bstride, int per_batch,
    bf16* __restrict__ h, bf16* __restrict__ l, int total)
{
    int i4 = (blockIdx.x * 256 + threadIdx.x) * 4;
    if (i4 >= total) return;
    int b = i4 / per_batch;
    int rem = i4 - b * per_batch;
    float4 v = *reinterpret_cast<const float4*>(src + (size_t)b * bstride + rem);
    bf16 h0 = __float2bfloat16(v.x), h1 = __float2bfloat16(v.y);
    bf16 h2 = __float2bfloat16(v.z), h3 = __float2bfloat16(v.w);
    bf16 l0 = __float2bfloat16(v.x - __bfloat162float(h0));
    bf16 l1 = __float2bfloat16(v.y - __bfloat162float(h1));
    bf16 l2 = __float2bfloat16(v.z - __bfloat162float(h2));
    bf16 l3 = __float2bfloat16(v.w - __bfloat162float(h3));
    __nv_bfloat162* hp = reinterpret_cast<__nv_bfloat162*>(h + i4);
    __nv_bfloat162* lp = reinterpret_cast<__nv_bfloat162*>(l + i4);
    hp[0] = __nv_bfloat162(h0, h1); hp[1] = __nv_bfloat162(h2, h3);
    lp[0] = __nv_bfloat162(l0, l1); lp[1] = __nv_bfloat162(l2, l3);
}

// ======================= tensor-core GEMM (mma.sync bf16 split) ============
// C[M,N] = A[M,192] @ B[192,N] fp32 via bf16 hi/lo planes.
// BM=128, BN=128, BK=32, 256 threads (8 warps: warp_m=wid&1 -> 64 rows,
// warp_n=wid>>1 -> 32 cols). Double-buffered cp.async.
#define BM 128
#define BN 128
#define BK 32
#define SA 40    // A smem row stride (bf16 elems): 80B, ldmatrix conflict-free
#define SB 136   // B smem row stride: 272B, conflict-free
#define A_PLANE_B (BM*SA*2)            // 10240 bytes
#define B_PLANE_B (BK*SB*2)            // 8704 bytes
#define OFF_AH 0
#define OFF_AL (A_PLANE_B)             // 10240
#define OFF_BH (2*A_PLANE_B)           // 20480
#define OFF_BL (2*A_PLANE_B + B_PLANE_B) // 29184
#define BUF_B  (2*A_PLANE_B + 2*B_PLANE_B) // 37888
#define SMEM_B (2*BUF_B)               // 75776

__global__ void __launch_bounds__(256) gemm_mma(
    const bf16* __restrict__ Ah, const bf16* __restrict__ Al,
    const bf16* __restrict__ Bh, const bf16* __restrict__ Bl,
    float* __restrict__ C, int Mreal, int ldc,
    size_t sAb, size_t sBb, size_t sCb)
{
    extern __shared__ char smem[];
    const uint32_t sb = smem_u32(smem);
    const int tid  = threadIdx.x;
    const int wid  = tid >> 5;
    const int lane = tid & 31;
    const int warp_m = wid & 1;
    const int warp_n = wid >> 1;

    const int bz = blockIdx.z;
    const bf16* Ahb = Ah + bz * sAb;
    const bf16* Alb = Al + bz * sAb;
    const bf16* Bhb = Bh + bz * sBb;
    const bf16* Blb = Bl + bz * sBb;
    float*      Cb  = C  + bz * sCb;

    const int m0 = blockIdx.y * BM;
    const int n0 = blockIdx.x * BN;

    float acc[4][4][4];
#pragma unroll
    for (int i = 0; i < 4; i++)
#pragma unroll
        for (int j = 0; j < 4; j++)
#pragma unroll
            for (int q = 0; q < 4; q++) acc[i][j][q] = 0.f;

    // --- async load of one K-chunk into buffer `buf` ---
    auto issue = [&](int kc, int buf) {
        uint32_t base = sb + buf * BUF_B;
        // A planes: 512 chunks of 16B each (row=c>>2, seg=c&3)
#pragma unroll
        for (int r = 0; r < 2; r++) {
            int c = tid * 2 + r;
            int row = c >> 2, seg = c & 3;
            int grow = m0 + row;
            int ok = (grow < Mreal) ? 16 : 0;
            int gr = (grow < Mreal) ? grow : 0;
            size_t go = (size_t)gr * KDIM + kc + seg * 8;
            uint32_t so = (uint32_t)(row * SA + seg * 8) * 2;
            cpa16(base + OFF_AH + so, Ahb + go, ok);
            cpa16(base + OFF_AL + so, Alb + go, ok);
        }
        // B planes: 512 chunks (row=c>>4, seg=c&15)
#pragma unroll
        for (int r = 0; r < 2; r++) {
            int c = tid * 2 + r;
            int row = c >> 4, seg = c & 15;
            size_t go = (size_t)(kc + row) * HW + n0 + seg * 8;
            uint32_t so = (uint32_t)(row * SB + seg * 8) * 2;
            cpa16(base + OFF_BH + so, Bhb + go, 16);
            cpa16(base + OFF_BL + so, Blb + go, 16);
        }
        CP_COMMIT();
    };

    issue(0, 0);

    const int arow = warp_m * 64 + (lane & 15);
    const int acolb = (lane >> 4) * 8;
    const int brow = (lane & 7) + ((lane >> 3) & 1) * 8;
    const int bcol = warp_n * 32 + ((lane >> 4) & 1) * 8;

    for (int ch = 0; ch < 6; ch++) {
        if (ch < 5) issue((ch + 1) * BK, (ch + 1) & 1);
        if (ch < 5) { CP_WAIT(1); } else { CP_WAIT(0); }
        __syncthreads();

        uint32_t base = sb + (ch & 1) * BUF_B;
#pragma unroll
        for (int ks = 0; ks < 2; ks++) {
            uint32_t ah[4][4], al[4][4], bh[2][4], bl[2][4];
            int acol = ks * 16 + acolb;
#pragma unroll
            for (int mt = 0; mt < 4; mt++) {
                uint32_t ao = (uint32_t)((arow + mt * 16) * SA + acol) * 2;
                ldsm4(base + OFF_AH + ao, ah[mt]);
                ldsm4(base + OFF_AL + ao, al[mt]);
            }
            int krow = ks * 16 + brow;
#pragma unroll
            for (int p = 0; p < 2; p++) {
                uint32_t bo = (uint32_t)(krow * SB + bcol + p * 16) * 2;
                ldsm4t(base + OFF_BH + bo, bh[p]);
                ldsm4t(base + OFF_BL + bo, bl[p]);
            }
#pragma unroll
            for (int mt = 0; mt < 4; mt++)
#pragma unroll
                for (int nt = 0; nt < 4; nt++) {
                    const uint32_t* bfh = &bh[nt >> 1][(nt & 1) * 2];
                    const uint32_t* bfl = &bl[nt >> 1][(nt & 1) * 2];
                    mma16816(acc[mt][nt], ah[mt], bfh);
                    mma16816(acc[mt][nt], ah[mt], bfl);
                    mma16816(acc[mt][nt], al[mt], bfh);
                }
        }
        __syncthreads();
    }

    // --- epilogue: fragment layout m16n8 -> gmem fp32 ---
    const int erow = lane >> 2;
    const int ecol = (lane & 3) * 2;
#pragma unroll
    for (int mt = 0; mt < 4; mt++) {
        int r0 = m0 + warp_m * 64 + mt * 16 + erow;
        int r1 = r0 + 8;
#pragma unroll
        for (int nt = 0; nt < 4; nt++) {
            int cc = n0 + warp_n * 32 + nt * 8 + ecol;
            if (r0 < Mreal)
                *reinterpret_cast<float2*>(Cb + (size_t)r0 * ldc + cc) =
                    make_float2(acc[mt][nt][0], acc[mt][nt][1]);
            if (r1 < Mreal)
                *reinterpret_cast<float2*>(Cb + (size_t)r1 * ldc + cc) =
                    make_float2(acc[mt][nt][2], acc[mt][nt][3]);
        }
    }
}

// ---------------- depthwise 3x3, SAME padding (cross-correlation) ----------
__global__ void dwconv3x3(const float* __restrict__ in, const float* __restrict__ wdw,
                          float* __restrict__ out)
{
    const int x  = blockIdx.x * 32 + threadIdx.x;
    const int y  = blockIdx.y * 8 + threadIdx.y;
    const int bc = blockIdx.z;           // b*C3 + o
    const int o  = bc % C3;
    const float* ip = in + (size_t)bc * HW;
    const float* wp = wdw + o * 9;

    float s = 0.f;
#pragma unroll
    for (int dy = 0; dy < 3; dy++) {
        int yy = y + dy - 1;
        if (yy < 0 || yy >= HH) continue;
#pragma unroll
        for (int dx = 0; dx < 3; dx++) {
            int xx = x + dx - 1;
            if (xx < 0 || xx >= WW) continue;
            s += ip[yy * WW + xx] * wp[dy * 3 + dx];
        }
    }
    out[(size_t)bc * HW + y * WW + x] = s;
}

// ---------------- per-row L2 norms of q,k over hw --------------------------
__global__ void __launch_bounds__(256) rownorm(const float* __restrict__ qkv2,
                                               float* __restrict__ norm)
{
    const int r = blockIdx.x;            // [0, BATCH*2*C0)
    const int b = r / (2 * C0);
    const int t = (r / C0) % 2;          // 0=q, 1=k
    const int c = r % C0;
    const float* p = qkv2 + ((size_t)b * C3 + t * C0 + c) * HW;

    float s = 0.f;
    for (int i = threadIdx.x * 4; i < HW; i += 1024) {
        float4 v = *reinterpret_cast<const float4*>(p + i);
        s += v.x * v.x + v.y * v.y + v.z * v.z + v.w * v.w;
    }
    __shared__ float red[256];
    red[threadIdx.x] = s;
    __syncthreads();
    for (int st = 128; st > 0; st >>= 1) {
        if (threadIdx.x < st) red[threadIdx.x] += red[threadIdx.x + st];
        __syncthreads();
    }
    if (threadIdx.x == 0) norm[r] = fmaxf(sqrtf(red[0]), 1e-12f);
}

// ---------------- zero the attn accumulator --------------------------------
__global__ void zero_attn(float* __restrict__ a)
{
    int i = blockIdx.x * 256 + threadIdx.x;
    if (i < BATCH * NH * HD * HD) a[i] = 0.f;
}

// ---------------- split-K q·k^T : 48x48 per (b,h), atomic accumulate -------
#define SPLITS 72
#define CHUNK (HW / SPLITS)   // 512
__global__ void __launch_bounds__(256) attn_qk(const float* __restrict__ qkv2,
                                               float* __restrict__ attn)
{
    const int split = blockIdx.x;
    const int bh = blockIdx.y;            // b*NH + h
    const int b = bh / NH, h = bh % NH;
    const float* qp = qkv2 + ((size_t)b * C3 +        h * HD) * HW;
    const float* kp = qkv2 + ((size_t)b * C3 + C0 +   h * HD) * HW;
    const int n0 = split * CHUNK;

    __shared__ float Qs[48][33];
    __shared__ float Ks[48][33];

    const int tid = threadIdx.x;
    const int tx = tid & 15;   // e-dir, 3 each
    const int ty = tid >> 4;   // d-dir, 3 each

    float acc[3][3] = {};

    for (int nb = 0; nb < CHUNK; nb += 32) {
#pragma unroll
        for (int r = 0; r < 6; r++) {
            int idx = tid + r * 256;
            int d = idx >> 5, nn = idx & 31;
            Qs[d][nn] = qp[(size_t)d * HW + n0 + nb + nn];
            Ks[d][nn] = kp[(size_t)d * HW + n0 + nb + nn];
        }
        __syncthreads();
#pragma unroll
        for (int kk = 0; kk < 32; kk++) {
            float a[3], bb[3];
#pragma unroll
            for (int i = 0; i < 3; i++) a[i]  = Qs[ty * 3 + i][kk];
#pragma unroll
            for (int j = 0; j < 3; j++) bb[j] = Ks[tx * 3 + j][kk];
#pragma unroll
            for (int i = 0; i < 3; i++)
#pragma unroll
                for (int j = 0; j < 3; j++) acc[i][j] += a[i] * bb[j];
        }
        __syncthreads();
    }

    float* ap = attn + (size_t)bh * HD * HD;
#pragma unroll
    for (int i = 0; i < 3; i++)
#pragma unroll
        for (int j = 0; j < 3; j++)
            atomicAdd(&ap[(ty * 3 + i) * HD + tx * 3 + j], acc[i][j]);
}

// ---------------- scale by norms + temperature, softmax over e -------------
__global__ void softmax_attn(float* __restrict__ attn, const float* __restrict__ norm,
                             const float* __restrict__ logtemp)
{
    const int bh = blockIdx.x;
    const int b = bh / NH, h = bh % NH;
    const int d = threadIdx.x;
    if (d >= HD) return;

    float lt = logtemp[h];
    float temp = (lt > 20.f ? lt : log1pf(expf(lt))) + 1e-6f;

    const float* nq = norm + (b * 2 + 0) * C0 + h * HD;
    const float* nk = norm + (b * 2 + 1) * C0 + h * HD;
    float* row = attn + ((size_t)bh * HD + d) * HD;
    const float qn = nq[d];

    float vals[HD];
    float mx = -1e30f;
#pragma unroll
    for (int e = 0; e < HD; e++) {
        float v = row[e] / (qn * nk[e]) * temp;
        vals[e] = v;
        mx = fmaxf(mx, v);
    }
    float s = 0.f;
#pragma unroll
    for (int e = 0; e < HD; e++) {
        vals[e] = expf(vals[e] - mx);
        s += vals[e];
    }
    float inv = 1.f / s;
#pragma unroll
    for (int e = 0; e < HD; e++) row[e] = vals[e] * inv;
}

// ---------------- W2[b] = w_proj @ blockdiag(attn[b]) -> bf16 hi/lo --------
__global__ void build_w2(const float* __restrict__ wproj, const float* __restrict__ attn,
                         bf16* __restrict__ w2h, bf16* __restrict__ w2l)
{
    int idx = blockIdx.x * 256 + threadIdx.x;
    if (idx >= BATCH * C0 * C0) return;
    int cc = idx % C0;
    int o  = (idx / C0) % C0;
    int b  = idx / (C0 * C0);
    int h = cc / HD, e = cc % HD;
    float s = 0.f;
#pragma unroll
    for (int d = 0; d < HD; d++)
        s += wproj[o * C0 + h * HD + d] * attn[(((size_t)b * NH + h) * HD + d) * HD + e];
    bf16 hi = __float2bfloat16(s);
    bf16 lo = __float2bfloat16(s - __bfloat162float(hi));
    w2h[idx] = hi;
    w2l[idx] = lo;
}

// ---------------- launcher -------------------------------------------------
extern "C" void kernel_launch(void* const* d_in, const int* in_sizes, int n_in,
                              void* d_out, int out_size)
{
    const float* x      = (const float*)d_in[0];  // [2,192,192,192]
    const float* w_qkv  = (const float*)d_in[1];  // [576,192]
    const float* w_dw   = (const float*)d_in[2];  // [576,1,3,3]
    const float* w_proj = (const float*)d_in[3];  // [192,192]
    const float* ltemp  = (const float*)d_in[4];  // [4,1,1]
    float* out = (float*)d_out;

    float *qkv1, *qkv2, *norm, *attn;
    bf16 *xh, *xl, *vh, *vl, *wqh, *wql, *w2h, *w2l;
    cudaGetSymbolAddress((void**)&qkv1, g_qkv1);
    cudaGetSymbolAddress((void**)&qkv2, g_qkv2);
    cudaGetSymbolAddress((void**)&norm, g_norm);
    cudaGetSymbolAddress((void**)&attn, g_attn);
    cudaGetSymbolAddress((void**)&xh,  g_xh);
    cudaGetSymbolAddress((void**)&xl,  g_xl);
    cudaGetSymbolAddress((void**)&vh,  g_vh);
    cudaGetSymbolAddress((void**)&vl,  g_vl);
    cudaGetSymbolAddress((void**)&wqh, g_wqh);
    cudaGetSymbolAddress((void**)&wql, g_wql);
    cudaGetSymbolAddress((void**)&w2h, g_w2h);
    cudaGetSymbolAddress((void**)&w2l, g_w2l);

    cudaFuncSetAttribute(gemm_mma, cudaFuncAttributeMaxDynamicSharedMemorySize, SMEM_B);

    // 0) split x and w_qkv to bf16 hi/lo planes
    {
        int total = BATCH * C0 * HW;
        split_batched<<<total / 4 / 256, 256>>>(x, (size_t)C0 * HW, C0 * HW, xh, xl, total);
        int wtot = C3 * C0;
        split_batched<<<(wtot / 4 + 255) / 256, 256>>>(w_qkv, wtot, wtot, wqh, wql, wtot);
    }
    // 1) qkv1 = w_qkv @ x : M=576, K=192, N=36864, batch=2
    {
        dim3 grid(HW / BN, (C3 + BM - 1) / BM, BATCH);
        gemm_mma<<<grid, 256, SMEM_B>>>(wqh, wql, xh, xl, qkv1,
                                        C3, HW, 0, (size_t)C0 * HW, (size_t)C3 * HW);
    }
    // 2) depthwise 3x3
    {
        dim3 grid(WW / 32, HH / 8, BATCH * C3);
        dwconv3x3<<<grid, dim3(32, 8)>>>(qkv1, w_dw, qkv2);
    }
    // 2b) split v (qkv2 channels [384,576)) to bf16 hi/lo
    {
        int total = BATCH * C0 * HW;
        split_batched<<<total / 4 / 256, 256>>>(qkv2 + (size_t)2 * C0 * HW,
                                                (size_t)C3 * HW, C0 * HW, vh, vl, total);
    }
    // 3) L2 norms of q,k rows
    rownorm<<<BATCH * 2 * C0, 256>>>(qkv2, norm);
    // 4) zero attn accumulator, then split-K q.k^T
    zero_attn<<<(BATCH * NH * HD * HD + 255) / 256, 256>>>(attn);
    {
        dim3 grid(SPLITS, BATCH * NH);
        attn_qk<<<grid, 256>>>(qkv2, attn);
    }
    // 5) softmax (with norm division + temperature)
    softmax_attn<<<BATCH * NH, 64>>>(attn, norm, ltemp);
    // 6) W2 = w_proj @ blockdiag(attn) -> bf16 hi/lo
    build_w2<<<(BATCH * C0 * C0 + 255) / 256, 256>>>(w_proj, attn, w2h, w2l);
    // 7) out = W2 @ v : M=192, K=192, N=36864, batch=2
    {
        dim3 grid(HW / BN, (C0 + BM - 1) / BM, BATCH);
        gemm_mma<<<grid, 256, SMEM_B>>>(w2h, w2l, vh, vl, out,
                                        C0, HW, (size_t)C0 * C0, (size_t)C0 * HW,
                                        (size_t)C0 * HW);
    }
}

// round 5
// speedup vs baseline: 2.3874x; 1.2250x over previous
#include <cuda_runtime.h>
#include <cuda_bf16.h>
#include <math.h>
#include <cstdint>

#define BATCH 2
#define C0 192
#define HH 192
#define WW 192
#define HW (HH*WW)          // 36864
#define C3 (3*C0)           // 576
#define NH 4
#define HD 48
#define KDIM 192

typedef __nv_bfloat16 bf16;

// ---------------- scratch (device globals; no allocs allowed) --------------
__device__ float g_qkv1[BATCH*C3*HW];      // after 1x1 conv
__device__ float g_qkv2[BATCH*C3*HW];      // after depthwise 3x3 (q,k only)
__device__ float g_normsq[BATCH*2*C0];     // [b][q|k][c]  sum of squares
__device__ float g_attn[BATCH*NH*HD*HD];   // raw dots -> softmaxed attn
__device__ bf16  g_xh[BATCH*C0*HW];        // x hi plane
__device__ bf16  g_xl[BATCH*C0*HW];        // x lo plane
__device__ bf16  g_vh[BATCH*C0*HW];        // v hi plane
__device__ bf16  g_vl[BATCH*C0*HW];        // v lo plane
__device__ bf16  g_wqh[C3*C0];             // w_qkv hi
__device__ bf16  g_wql[C3*C0];             // w_qkv lo
__device__ bf16  g_w2h[BATCH*C0*C0];       // w2 hi
__device__ bf16  g_w2l[BATCH*C0*C0];       // w2 lo

// ======================= small helpers =====================================
__device__ __forceinline__ uint32_t smem_u32(const void* p) {
    uint32_t a;
    asm("{ .reg .u64 t; cvta.to.shared.u64 t, %1; cvt.u32.u64 %0, t; }"
        : "=r"(a) : "l"(p));
    return a;
}
__device__ __forceinline__ void ldsm4(uint32_t addr, uint32_t* r) {
    asm volatile("ldmatrix.sync.aligned.m8n8.x4.shared.b16 {%0,%1,%2,%3}, [%4];"
        : "=r"(r[0]), "=r"(r[1]), "=r"(r[2]), "=r"(r[3]) : "r"(addr));
}
__device__ __forceinline__ void ldsm4t(uint32_t addr, uint32_t* r) {
    asm volatile("ldmatrix.sync.aligned.m8n8.x4.trans.shared.b16 {%0,%1,%2,%3}, [%4];"
        : "=r"(r[0]), "=r"(r[1]), "=r"(r[2]), "=r"(r[3]) : "r"(addr));
}
__device__ __forceinline__ void mma16816(float* d, const uint32_t* a, const uint32_t* b) {
    asm volatile(
        "mma.sync.aligned.m16n8k16.row.col.f32.bf16.bf16.f32 "
        "{%0,%1,%2,%3}, {%4,%5,%6,%7}, {%8,%9}, {%0,%1,%2,%3};"
        : "+f"(d[0]), "+f"(d[1]), "+f"(d[2]), "+f"(d[3])
        : "r"(a[0]), "r"(a[1]), "r"(a[2]), "r"(a[3]), "r"(b[0]), "r"(b[1]));
}
__device__ __forceinline__ void cpa16(uint32_t dst, const void* src, int bytes) {
    asm volatile("cp.async.cg.shared.global [%0], [%1], 16, %2;"
        :: "r"(dst), "l"(src), "r"(bytes));
}
#define CP_COMMIT() asm volatile("cp.async.commit_group;")
#define CP_WAIT(n)  asm volatile("cp.async.wait_group %0;" :: "n"(n))

// ======================= split-bf16 conversion =============================
__global__ void __launch_bounds__(256) split_batched(
    const float* __restrict__ src, size_t bstride, int per_batch,
    bf16* __restrict__ h, bf16* __restrict__ l, int total)
{
    int i4 = (blockIdx.x * 256 + threadIdx.x) * 4;
    if (i4 >= total) return;
    int b = i4 / per_batch;
    int rem = i4 - b * per_batch;
    float4 v = *reinterpret_cast<const float4*>(src + (size_t)b * bstride + rem);
    bf16 h0 = __float2bfloat16(v.x), h1 = __float2bfloat16(v.y);
    bf16 h2 = __float2bfloat16(v.z), h3 = __float2bfloat16(v.w);
    bf16 l0 = __float2bfloat16(v.x - __bfloat162float(h0));
    bf16 l1 = __float2bfloat16(v.y - __bfloat162float(h1));
    bf16 l2 = __float2bfloat16(v.z - __bfloat162float(h2));
    bf16 l3 = __float2bfloat16(v.w - __bfloat162float(h3));
    __nv_bfloat162* hp = reinterpret_cast<__nv_bfloat162*>(h + i4);
    __nv_bfloat162* lp = reinterpret_cast<__nv_bfloat162*>(l + i4);
    hp[0] = __nv_bfloat162(h0, h1); hp[1] = __nv_bfloat162(h2, h3);
    lp[0] = __nv_bfloat162(l0, l1); lp[1] = __nv_bfloat162(l2, l3);
}

// ======================= tensor-core GEMM (mma.sync bf16 split) ============
#define BM 128
#define BN 128
#define BK 32
#define SA 40
#define SB 136
#define A_PLANE_B (BM*SA*2)
#define B_PLANE_B (BK*SB*2)
#define OFF_AH 0
#define OFF_AL (A_PLANE_B)
#define OFF_BH (2*A_PLANE_B)
#define OFF_BL (2*A_PLANE_B + B_PLANE_B)
#define BUF_B  (2*A_PLANE_B + 2*B_PLANE_B)
#define SMEM_B (2*BUF_B)

__global__ void __launch_bounds__(256) gemm_mma(
    const bf16* __restrict__ Ah, const bf16* __restrict__ Al,
    const bf16* __restrict__ Bh, const bf16* __restrict__ Bl,
    float* __restrict__ C, int Mreal, int ldc,
    size_t sAb, size_t sBb, size_t sCb)
{
    extern __shared__ char smem[];
    const uint32_t sb = smem_u32(smem);
    const int tid  = threadIdx.x;
    const int wid  = tid >> 5;
    const int lane = tid & 31;
    const int warp_m = wid & 1;
    const int warp_n = wid >> 1;

    const int bz = blockIdx.z;
    const bf16* Ahb = Ah + bz * sAb;
    const bf16* Alb = Al + bz * sAb;
    const bf16* Bhb = Bh + bz * sBb;
    const bf16* Blb = Bl + bz * sBb;
    float*      Cb  = C  + bz * sCb;

    const int m0 = blockIdx.y * BM;
    const int n0 = blockIdx.x * BN;

    float acc[4][4][4];
#pragma unroll
    for (int i = 0; i < 4; i++)
#pragma unroll
        for (int j = 0; j < 4; j++)
#pragma unroll
            for (int q = 0; q < 4; q++) acc[i][j][q] = 0.f;

    auto issue = [&](int kc, int buf) {
        uint32_t base = sb + buf * BUF_B;
#pragma unroll
        for (int r = 0; r < 2; r++) {
            int c = tid * 2 + r;
            int row = c >> 2, seg = c & 3;
            int grow = m0 + row;
            int ok = (grow < Mreal) ? 16 : 0;
            int gr = (grow < Mreal) ? grow : 0;
            size_t go = (size_t)gr * KDIM + kc + seg * 8;
            uint32_t so = (uint32_t)(row * SA + seg * 8) * 2;
            cpa16(base + OFF_AH + so, Ahb + go, ok);
            cpa16(base + OFF_AL + so, Alb + go, ok);
        }
#pragma unroll
        for (int r = 0; r < 2; r++) {
            int c = tid * 2 + r;
            int row = c >> 4, seg = c & 15;
            size_t go = (size_t)(kc + row) * HW + n0 + seg * 8;
            uint32_t so = (uint32_t)(row * SB + seg * 8) * 2;
            cpa16(base + OFF_BH + so, Bhb + go, 16);
            cpa16(base + OFF_BL + so, Blb + go, 16);
        }
        CP_COMMIT();
    };

    issue(0, 0);

    const int arow = warp_m * 64 + (lane & 15);
    const int acolb = (lane >> 4) * 8;
    const int brow = (lane & 7) + ((lane >> 3) & 1) * 8;
    const int bcol = warp_n * 32 + ((lane >> 4) & 1) * 8;

    for (int ch = 0; ch < 6; ch++) {
        if (ch < 5) issue((ch + 1) * BK, (ch + 1) & 1);
        if (ch < 5) { CP_WAIT(1); } else { CP_WAIT(0); }
        __syncthreads();

        uint32_t base = sb + (ch & 1) * BUF_B;
#pragma unroll
        for (int ks = 0; ks < 2; ks++) {
            uint32_t ah[4][4], al[4][4], bh[2][4], bl[2][4];
            int acol = ks * 16 + acolb;
#pragma unroll
            for (int mt = 0; mt < 4; mt++) {
                uint32_t ao = (uint32_t)((arow + mt * 16) * SA + acol) * 2;
                ldsm4(base + OFF_AH + ao, ah[mt]);
                ldsm4(base + OFF_AL + ao, al[mt]);
            }
            int krow = ks * 16 + brow;
#pragma unroll
            for (int p = 0; p < 2; p++) {
                uint32_t bo = (uint32_t)(krow * SB + bcol + p * 16) * 2;
                ldsm4t(base + OFF_BH + bo, bh[p]);
                ldsm4t(base + OFF_BL + bo, bl[p]);
            }
#pragma unroll
            for (int mt = 0; mt < 4; mt++)
#pragma unroll
                for (int nt = 0; nt < 4; nt++) {
                    const uint32_t* bfh = &bh[nt >> 1][(nt & 1) * 2];
                    const uint32_t* bfl = &bl[nt >> 1][(nt & 1) * 2];
                    mma16816(acc[mt][nt], ah[mt], bfh);
                    mma16816(acc[mt][nt], ah[mt], bfl);
                    mma16816(acc[mt][nt], al[mt], bfh);
                }
        }
        __syncthreads();
    }

    const int erow = lane >> 2;
    const int ecol = (lane & 3) * 2;
#pragma unroll
    for (int mt = 0; mt < 4; mt++) {
        int r0 = m0 + warp_m * 64 + mt * 16 + erow;
        int r1 = r0 + 8;
#pragma unroll
        for (int nt = 0; nt < 4; nt++) {
            int cc = n0 + warp_n * 32 + nt * 8 + ecol;
            if (r0 < Mreal)
                *reinterpret_cast<float2*>(Cb + (size_t)r0 * ldc + cc) =
                    make_float2(acc[mt][nt][0], acc[mt][nt][1]);
            if (r1 < Mreal)
                *reinterpret_cast<float2*>(Cb + (size_t)r1 * ldc + cc) =
                    make_float2(acc[mt][nt][2], acc[mt][nt][3]);
        }
    }
}

// ============ fused depthwise 3x3 + qk-normsq + v-split ====================
// Block = one (b, channel) stripe, 48x8 threads, each thread 4 outputs in x.
#define DW_TX 48
#define DW_TY 8
__global__ void __launch_bounds__(DW_TX*DW_TY) dwconv_fused(
    const float* __restrict__ in, const float* __restrict__ wdw,
    float* __restrict__ qkout, bf16* __restrict__ vh, bf16* __restrict__ vl,
    float* __restrict__ normsq)
{
    const int bc = blockIdx.y;           // b*C3 + o
    const int b  = bc / C3;
    const int o  = bc % C3;
    const float* ip = in + (size_t)bc * HW;

    float w[9];
#pragma unroll
    for (int i = 0; i < 9; i++) w[i] = __ldg(wdw + o * 9 + i);

    const int y  = blockIdx.x * DW_TY + threadIdx.y;
    const int x0 = threadIdx.x * 4;

    float a0 = 0.f, a1 = 0.f, a2 = 0.f, a3 = 0.f;
#pragma unroll
    for (int dy = 0; dy < 3; dy++) {
        int yy = y + dy - 1;
        if (yy < 0 || yy >= HH) continue;
        const float* rp = ip + (size_t)yy * WW;
        float4 c  = *reinterpret_cast<const float4*>(rp + x0);
        float lft = (x0 > 0)       ? rp[x0 - 1] : 0.f;
        float rgt = (x0 + 4 < WW)  ? rp[x0 + 4] : 0.f;
        float w0 = w[dy*3], w1 = w[dy*3+1], w2 = w[dy*3+2];
        a0 += w0*lft + w1*c.x + w2*c.y;
        a1 += w0*c.x + w1*c.y + w2*c.z;
        a2 += w0*c.y + w1*c.z + w2*c.w;
        a3 += w0*c.z + w1*c.w + w2*rgt;
    }

    if (o < 2 * C0) {
        // q/k channel: write fp32 + accumulate sum of squares
        float* op = qkout + (size_t)bc * HW + (size_t)y * WW + x0;
        *reinterpret_cast<float4*>(op) = make_float4(a0, a1, a2, a3);

        // warp shuffle reduce (exact, no non-pot tree issues)
        float s = a0*a0 + a1*a1 + a2*a2 + a3*a3;
#pragma unroll
        for (int off = 16; off > 0; off >>= 1)
            s += __shfl_xor_sync(0xffffffffu, s, off);
        int lane = (threadIdx.y * DW_TX + threadIdx.x) & 31;
        if (lane == 0) {
            int t = o / C0, c = o % C0;
            atomicAdd(&normsq[(b * 2 + t) * C0 + c], s);
        }
    } else {
        // v channel: split to bf16 hi/lo directly
        int vc = o - 2 * C0;
        size_t off = ((size_t)b * C0 + vc) * HW + (size_t)y * WW + x0;
        bf16 h0 = __float2bfloat16(a0), h1 = __float2bfloat16(a1);
        bf16 h2 = __float2bfloat16(a2), h3 = __float2bfloat16(a3);
        bf16 l0 = __float2bfloat16(a0 - __bfloat162float(h0));
        bf16 l1 = __float2bfloat16(a1 - __bfloat162float(h1));
        bf16 l2 = __float2bfloat16(a2 - __bfloat162float(h2));
        bf16 l3 = __float2bfloat16(a3 - __bfloat162float(h3));
        __nv_bfloat162* hp = reinterpret_cast<__nv_bfloat162*>(vh + off);
        __nv_bfloat162* lp = reinterpret_cast<__nv_bfloat162*>(vl + off);
        hp[0] = __nv_bfloat162(h0, h1); hp[1] = __nv_bfloat162(h2, h3);
        lp[0] = __nv_bfloat162(l0, l1); lp[1] = __nv_bfloat162(l2, l3);
    }
}

// ---------------- zero attn + normsq ---------------------------------------
__global__ void zero_small(float* __restrict__ attn, float* __restrict__ normsq)
{
    int i = blockIdx.x * 256 + threadIdx.x;
    if (i < BATCH * NH * HD * HD) attn[i] = 0.f;
    if (i < BATCH * 2 * C0) normsq[i] = 0.f;
}

// ---------------- split-K q·k^T : 48x48 per (b,h), atomic accumulate -------
#define SPLITS 72
#define CHUNK (HW / SPLITS)   // 512
__global__ void __launch_bounds__(256) attn_qk(const float* __restrict__ qkv2,
                                               float* __restrict__ attn)
{
    const int split = blockIdx.x;
    const int bh = blockIdx.y;
    const int b = bh / NH, h = bh % NH;
    const float* qp = qkv2 + ((size_t)b * C3 +        h * HD) * HW;
    const float* kp = qkv2 + ((size_t)b * C3 + C0 +   h * HD) * HW;
    const int n0 = split * CHUNK;

    __shared__ float Qs[48][33];
    __shared__ float Ks[48][33];

    const int tid = threadIdx.x;
    const int tx = tid & 15;
    const int ty = tid >> 4;

    float acc[3][3] = {};

    for (int nb = 0; nb < CHUNK; nb += 32) {
#pragma unroll
        for (int r = 0; r < 6; r++) {
            int idx = tid + r * 256;
            int d = idx >> 5, nn = idx & 31;
            Qs[d][nn] = qp[(size_t)d * HW + n0 + nb + nn];
            Ks[d][nn] = kp[(size_t)d * HW + n0 + nb + nn];
        }
        __syncthreads();
#pragma unroll
        for (int kk = 0; kk < 32; kk++) {
            float a[3], bb[3];
#pragma unroll
            for (int i = 0; i < 3; i++) a[i]  = Qs[ty * 3 + i][kk];
#pragma unroll
            for (int j = 0; j < 3; j++) bb[j] = Ks[tx * 3 + j][kk];
#pragma unroll
            for (int i = 0; i < 3; i++)
#pragma unroll
                for (int j = 0; j < 3; j++) acc[i][j] += a[i] * bb[j];
        }
        __syncthreads();
    }

    float* ap = attn + (size_t)bh * HD * HD;
#pragma unroll
    for (int i = 0; i < 3; i++)
#pragma unroll
        for (int j = 0; j < 3; j++)
            atomicAdd(&ap[(ty * 3 + i) * HD + tx * 3 + j], acc[i][j]);
}

// ---------------- scale by norms + temperature, softmax over e -------------
__global__ void softmax_attn(float* __restrict__ attn, const float* __restrict__ normsq,
                             const float* __restrict__ logtemp)
{
    const int bh = blockIdx.x;
    const int b = bh / NH, h = bh % NH;
    const int d = threadIdx.x;
    if (d >= HD) return;

    float lt = logtemp[h];
    float temp = (lt > 20.f ? lt : log1pf(expf(lt))) + 1e-6f;

    const float* nq = normsq + (b * 2 + 0) * C0 + h * HD;
    const float* nk = normsq + (b * 2 + 1) * C0 + h * HD;
    float* row = attn + ((size_t)bh * HD + d) * HD;
    const float qn = fmaxf(sqrtf(nq[d]), 1e-12f);

    float vals[HD];
    float mx = -1e30f;
#pragma unroll
    for (int e = 0; e < HD; e++) {
        float kn = fmaxf(sqrtf(nk[e]), 1e-12f);
        float v = row[e] / (qn * kn) * temp;
        vals[e] = v;
        mx = fmaxf(mx, v);
    }
    float s = 0.f;
#pragma unroll
    for (int e = 0; e < HD; e++) {
        vals[e] = expf(vals[e] - mx);
        s += vals[e];
    }
    float inv = 1.f / s;
#pragma unroll
    for (int e = 0; e < HD; e++) row[e] = vals[e] * inv;
}

// ---------------- W2[b] = w_proj @ blockdiag(attn[b]) -> bf16 hi/lo --------
__global__ void build_w2(const float* __restrict__ wproj, const float* __restrict__ attn,
                         bf16* __restrict__ w2h, bf16* __restrict__ w2l)
{
    int idx = blockIdx.x * 256 + threadIdx.x;
    if (idx >= BATCH * C0 * C0) return;
    int cc = idx % C0;
    int o  = (idx / C0) % C0;
    int b  = idx / (C0 * C0);
    int h = cc / HD, e = cc % HD;
    float s = 0.f;
#pragma unroll
    for (int d = 0; d < HD; d++)
        s += wproj[o * C0 + h * HD + d] * attn[(((size_t)b * NH + h) * HD + d) * HD + e];
    bf16 hi = __float2bfloat16(s);
    bf16 lo = __float2bfloat16(s - __bfloat162float(hi));
    w2h[idx] = hi;
    w2l[idx] = lo;
}

// ---------------- launcher -------------------------------------------------
extern "C" void kernel_launch(void* const* d_in, const int* in_sizes, int n_in,
                              void* d_out, int out_size)
{
    const float* x      = (const float*)d_in[0];
    const float* w_qkv  = (const float*)d_in[1];
    const float* w_dw   = (const float*)d_in[2];
    const float* w_proj = (const float*)d_in[3];
    const float* ltemp  = (const float*)d_in[4];
    float* out = (float*)d_out;

    float *qkv1, *qkv2, *normsq, *attn;
    bf16 *xh, *xl, *vh, *vl, *wqh, *wql, *w2h, *w2l;
    cudaGetSymbolAddress((void**)&qkv1, g_qkv1);
    cudaGetSymbolAddress((void**)&qkv2, g_qkv2);
    cudaGetSymbolAddress((void**)&normsq, g_normsq);
    cudaGetSymbolAddress((void**)&attn, g_attn);
    cudaGetSymbolAddress((void**)&xh,  g_xh);
    cudaGetSymbolAddress((void**)&xl,  g_xl);
    cudaGetSymbolAddress((void**)&vh,  g_vh);
    cudaGetSymbolAddress((void**)&vl,  g_vl);
    cudaGetSymbolAddress((void**)&wqh, g_wqh);
    cudaGetSymbolAddress((void**)&wql, g_wql);
    cudaGetSymbolAddress((void**)&w2h, g_w2h);
    cudaGetSymbolAddress((void**)&w2l, g_w2l);

    cudaFuncSetAttribute(gemm_mma, cudaFuncAttributeMaxDynamicSharedMemorySize, SMEM_B);

    // 0) split x and w_qkv to bf16 hi/lo planes; zero accumulators
    {
        int total = BATCH * C0 * HW;
        split_batched<<<total / 4 / 256, 256>>>(x, (size_t)C0 * HW, C0 * HW, xh, xl, total);
        int wtot = C3 * C0;
        split_batched<<<(wtot / 4 + 255) / 256, 256>>>(w_qkv, wtot, wtot, wqh, wql, wtot);
        zero_small<<<(BATCH * NH * HD * HD + 255) / 256, 256>>>(attn, normsq);
    }
    // 1) qkv1 = w_qkv @ x
    {
        dim3 grid(HW / BN, (C3 + BM - 1) / BM, BATCH);
        gemm_mma<<<grid, 256, SMEM_B>>>(wqh, wql, xh, xl, qkv1,
                                        C3, HW, 0, (size_t)C0 * HW, (size_t)C3 * HW);
    }
    // 2) fused depthwise 3x3 + qk normsq + v split
    {
        dim3 grid(HH / DW_TY, BATCH * C3);
        dwconv_fused<<<grid, dim3(DW_TX, DW_TY)>>>(qkv1, w_dw, qkv2, vh, vl, normsq);
    }
    // 3) split-K q.k^T
    {
        dim3 grid(SPLITS, BATCH * NH);
        attn_qk<<<grid, 256>>>(qkv2, attn);
    }
    // 4) softmax
    softmax_attn<<<BATCH * NH, 64>>>(attn, normsq, ltemp);
    // 5) W2
    build_w2<<<(BATCH * C0 * C0 + 255) / 256, 256>>>(w_proj, attn, w2h, w2l);
    // 6) out = W2 @ v
    {
        dim3 grid(HW / BN, (C0 + BM - 1) / BM, BATCH);
        gemm_mma<<<grid, 256, SMEM_B>>>(w2h, w2l, vh, vl, out,
                                        C0, HW, (size_t)C0 * C0, (size_t)C0 * HW,
                                        (size_t)C0 * HW);
    }
}

// round 6
// speedup vs baseline: 2.4875x; 1.0419x over previous
#include <cuda_runtime.h>
#include <cuda_bf16.h>
#include <math.h>
#include <cstdint>

#define BATCH 2
#define C0 192
#define HH 192
#define WW 192
#define HW (HH*WW)          // 36864
#define C3 (3*C0)           // 576
#define NH 4
#define HD 48
#define KDIM 192

typedef __nv_bfloat16 bf16;

// ---------------- scratch (device globals; no allocs allowed) --------------
__device__ float g_qkv1[BATCH*C3*HW];      // after 1x1 conv
__device__ float g_qkv2[BATCH*C3*HW];      // after depthwise 3x3 (q,k only)
__device__ float g_normsq[BATCH*2*C0];     // [b][q|k][c]  sum of squares
__device__ float g_attn[BATCH*NH*HD*HD];   // raw dots -> softmaxed attn
__device__ bf16  g_xh[BATCH*C0*HW];        // x hi plane
__device__ bf16  g_xl[BATCH*C0*HW];        // x lo plane
__device__ bf16  g_vh[BATCH*C0*HW];        // v hi plane
__device__ bf16  g_vl[BATCH*C0*HW];        // v lo plane
__device__ bf16  g_wqh[C3*C0];             // w_qkv hi
__device__ bf16  g_wql[C3*C0];             // w_qkv lo
__device__ bf16  g_w2h[BATCH*C0*C0];       // w2 hi
__device__ bf16  g_w2l[BATCH*C0*C0];       // w2 lo

// ======================= small helpers =====================================
__device__ __forceinline__ uint32_t smem_u32(const void* p) {
    uint32_t a;
    asm("{ .reg .u64 t; cvta.to.shared.u64 t, %1; cvt.u32.u64 %0, t; }"
        : "=r"(a) : "l"(p));
    return a;
}
__device__ __forceinline__ void ldsm4(uint32_t addr, uint32_t* r) {
    asm volatile("ldmatrix.sync.aligned.m8n8.x4.shared.b16 {%0,%1,%2,%3}, [%4];"
        : "=r"(r[0]), "=r"(r[1]), "=r"(r[2]), "=r"(r[3]) : "r"(addr));
}
__device__ __forceinline__ void ldsm4t(uint32_t addr, uint32_t* r) {
    asm volatile("ldmatrix.sync.aligned.m8n8.x4.trans.shared.b16 {%0,%1,%2,%3}, [%4];"
        : "=r"(r[0]), "=r"(r[1]), "=r"(r[2]), "=r"(r[3]) : "r"(addr));
}
__device__ __forceinline__ void mma16816(float* d, const uint32_t* a, const uint32_t* b) {
    asm volatile(
        "mma.sync.aligned.m16n8k16.row.col.f32.bf16.bf16.f32 "
        "{%0,%1,%2,%3}, {%4,%5,%6,%7}, {%8,%9}, {%0,%1,%2,%3};"
        : "+f"(d[0]), "+f"(d[1]), "+f"(d[2]), "+f"(d[3])
        : "r"(a[0]), "r"(a[1]), "r"(a[2]), "r"(a[3]), "r"(b[0]), "r"(b[1]));
}
__device__ __forceinline__ void cpa16(uint32_t dst, const void* src, int bytes) {
    asm volatile("cp.async.cg.shared.global [%0], [%1], 16, %2;"
        :: "r"(dst), "l"(src), "r"(bytes));
}
#define CP_COMMIT() asm volatile("cp.async.commit_group;")
#define CP_WAIT(n)  asm volatile("cp.async.wait_group %0;" :: "n"(n))

// ======================= split-bf16 conversion =============================
__global__ void __launch_bounds__(256) split_batched(
    const float* __restrict__ src, size_t bstride, int per_batch,
    bf16* __restrict__ h, bf16* __restrict__ l, int total)
{
    int i4 = (blockIdx.x * 256 + threadIdx.x) * 4;
    if (i4 >= total) return;
    int b = i4 / per_batch;
    int rem = i4 - b * per_batch;
    float4 v = *reinterpret_cast<const float4*>(src + (size_t)b * bstride + rem);
    bf16 h0 = __float2bfloat16(v.x), h1 = __float2bfloat16(v.y);
    bf16 h2 = __float2bfloat16(v.z), h3 = __float2bfloat16(v.w);
    bf16 l0 = __float2bfloat16(v.x - __bfloat162float(h0));
    bf16 l1 = __float2bfloat16(v.y - __bfloat162float(h1));
    bf16 l2 = __float2bfloat16(v.z - __bfloat162float(h2));
    bf16 l3 = __float2bfloat16(v.w - __bfloat162float(h3));
    __nv_bfloat162* hp = reinterpret_cast<__nv_bfloat162*>(h + i4);
    __nv_bfloat162* lp = reinterpret_cast<__nv_bfloat162*>(l + i4);
    hp[0] = __nv_bfloat162(h0, h1); hp[1] = __nv_bfloat162(h2, h3);
    lp[0] = __nv_bfloat162(l0, l1); lp[1] = __nv_bfloat162(l2, l3);
}

// ======================= tensor-core GEMM (mma.sync bf16 split) ============
// 3-stage cp.async pipeline, one __syncthreads per K-chunk.
#define BM 128
#define BN 128
#define BK 32
#define NCHUNK (KDIM/BK)     // 6
#define SA 40
#define SB 136
#define A_PLANE_B (BM*SA*2)
#define B_PLANE_B (BK*SB*2)
#define OFF_AH 0
#define OFF_AL (A_PLANE_B)
#define OFF_BH (2*A_PLANE_B)
#define OFF_BL (2*A_PLANE_B + B_PLANE_B)
#define BUF_B  (2*A_PLANE_B + 2*B_PLANE_B)   // 37888
#define NSTAGE 3
#define SMEM_B (NSTAGE*BUF_B)                // 113664

__global__ void __launch_bounds__(256) gemm_mma(
    const bf16* __restrict__ Ah, const bf16* __restrict__ Al,
    const bf16* __restrict__ Bh, const bf16* __restrict__ Bl,
    float* __restrict__ C, int Mreal, int ldc,
    size_t sAb, size_t sBb, size_t sCb)
{
    extern __shared__ char smem[];
    const uint32_t sb = smem_u32(smem);
    const int tid  = threadIdx.x;
    const int wid  = tid >> 5;
    const int lane = tid & 31;
    const int warp_m = wid & 1;
    const int warp_n = wid >> 1;

    const int bz = blockIdx.z;
    const bf16* Ahb = Ah + bz * sAb;
    const bf16* Alb = Al + bz * sAb;
    const bf16* Bhb = Bh + bz * sBb;
    const bf16* Blb = Bl + bz * sBb;
    float*      Cb  = C  + bz * sCb;

    const int m0 = blockIdx.y * BM;
    const int n0 = blockIdx.x * BN;

    float acc[4][4][4];
#pragma unroll
    for (int i = 0; i < 4; i++)
#pragma unroll
        for (int j = 0; j < 4; j++)
#pragma unroll
            for (int q = 0; q < 4; q++) acc[i][j][q] = 0.f;

    auto issue = [&](int kc, int buf) {
        uint32_t base = sb + buf * BUF_B;
#pragma unroll
        for (int r = 0; r < 2; r++) {
            int c = tid * 2 + r;
            int row = c >> 2, seg = c & 3;
            int grow = m0 + row;
            int ok = (grow < Mreal) ? 16 : 0;
            int gr = (grow < Mreal) ? grow : 0;
            size_t go = (size_t)gr * KDIM + kc + seg * 8;
            uint32_t so = (uint32_t)(row * SA + seg * 8) * 2;
            cpa16(base + OFF_AH + so, Ahb + go, ok);
            cpa16(base + OFF_AL + so, Alb + go, ok);
        }
#pragma unroll
        for (int r = 0; r < 2; r++) {
            int c = tid * 2 + r;
            int row = c >> 4, seg = c & 15;
            size_t go = (size_t)(kc + row) * HW + n0 + seg * 8;
            uint32_t so = (uint32_t)(row * SB + seg * 8) * 2;
            cpa16(base + OFF_BH + so, Bhb + go, 16);
            cpa16(base + OFF_BL + so, Blb + go, 16);
        }
        CP_COMMIT();
    };

    // prologue: 2 chunks in flight
    issue(0, 0);
    issue(BK, 1);

    const int arow = warp_m * 64 + (lane & 15);
    const int acolb = (lane >> 4) * 8;
    const int brow = (lane & 7) + ((lane >> 3) & 1) * 8;
    const int bcol = warp_n * 32 + ((lane >> 4) & 1) * 8;

    int buf = 0;
    for (int ch = 0; ch < NCHUNK; ch++) {
        if (ch < NCHUNK - 1) { CP_WAIT(1); } else { CP_WAIT(0); }
        __syncthreads();
        if (ch < NCHUNK - 2) {
            int nb = buf + 2; if (nb >= NSTAGE) nb -= NSTAGE;
            issue((ch + 2) * BK, nb);
        }

        uint32_t base = sb + buf * BUF_B;
#pragma unroll
        for (int ks = 0; ks < 2; ks++) {
            uint32_t ah[4][4], al[4][4], bh[2][4], bl[2][4];
            int acol = ks * 16 + acolb;
#pragma unroll
            for (int mt = 0; mt < 4; mt++) {
                uint32_t ao = (uint32_t)((arow + mt * 16) * SA + acol) * 2;
                ldsm4(base + OFF_AH + ao, ah[mt]);
                ldsm4(base + OFF_AL + ao, al[mt]);
            }
            int krow = ks * 16 + brow;
#pragma unroll
            for (int p = 0; p < 2; p++) {
                uint32_t bo = (uint32_t)(krow * SB + bcol + p * 16) * 2;
                ldsm4t(base + OFF_BH + bo, bh[p]);
                ldsm4t(base + OFF_BL + bo, bl[p]);
            }
#pragma unroll
            for (int mt = 0; mt < 4; mt++)
#pragma unroll
                for (int nt = 0; nt < 4; nt++) {
                    const uint32_t* bfh = &bh[nt >> 1][(nt & 1) * 2];
                    const uint32_t* bfl = &bl[nt >> 1][(nt & 1) * 2];
                    mma16816(acc[mt][nt], ah[mt], bfh);
                    mma16816(acc[mt][nt], ah[mt], bfl);
                    mma16816(acc[mt][nt], al[mt], bfh);
                }
        }
        buf++; if (buf >= NSTAGE) buf = 0;
    }

    const int erow = lane >> 2;
    const int ecol = (lane & 3) * 2;
#pragma unroll
    for (int mt = 0; mt < 4; mt++) {
        int r0 = m0 + warp_m * 64 + mt * 16 + erow;
        int r1 = r0 + 8;
#pragma unroll
        for (int nt = 0; nt < 4; nt++) {
            int cc = n0 + warp_n * 32 + nt * 8 + ecol;
            if (r0 < Mreal)
                *reinterpret_cast<float2*>(Cb + (size_t)r0 * ldc + cc) =
                    make_float2(acc[mt][nt][0], acc[mt][nt][1]);
            if (r1 < Mreal)
                *reinterpret_cast<float2*>(Cb + (size_t)r1 * ldc + cc) =
                    make_float2(acc[mt][nt][2], acc[mt][nt][3]);
        }
    }
}

// ============ fused depthwise 3x3 + qk-normsq + v-split ====================
#define DW_TX 48
#define DW_TY 8
__global__ void __launch_bounds__(DW_TX*DW_TY) dwconv_fused(
    const float* __restrict__ in, const float* __restrict__ wdw,
    float* __restrict__ qkout, bf16* __restrict__ vh, bf16* __restrict__ vl,
    float* __restrict__ normsq)
{
    const int bc = blockIdx.y;           // b*C3 + o
    const int b  = bc / C3;
    const int o  = bc % C3;
    const float* ip = in + (size_t)bc * HW;

    float w[9];
#pragma unroll
    for (int i = 0; i < 9; i++) w[i] = __ldg(wdw + o * 9 + i);

    const int y  = blockIdx.x * DW_TY + threadIdx.y;
    const int x0 = threadIdx.x * 4;

    float a0 = 0.f, a1 = 0.f, a2 = 0.f, a3 = 0.f;
#pragma unroll
    for (int dy = 0; dy < 3; dy++) {
        int yy = y + dy - 1;
        if (yy < 0 || yy >= HH) continue;
        const float* rp = ip + (size_t)yy * WW;
        float4 c  = *reinterpret_cast<const float4*>(rp + x0);
        float lft = (x0 > 0)       ? rp[x0 - 1] : 0.f;
        float rgt = (x0 + 4 < WW)  ? rp[x0 + 4] : 0.f;
        float w0 = w[dy*3], w1 = w[dy*3+1], w2 = w[dy*3+2];
        a0 += w0*lft + w1*c.x + w2*c.y;
        a1 += w0*c.x + w1*c.y + w2*c.z;
        a2 += w0*c.y + w1*c.z + w2*c.w;
        a3 += w0*c.z + w1*c.w + w2*rgt;
    }

    if (o < 2 * C0) {
        float* op = qkout + (size_t)bc * HW + (size_t)y * WW + x0;
        *reinterpret_cast<float4*>(op) = make_float4(a0, a1, a2, a3);

        float s = a0*a0 + a1*a1 + a2*a2 + a3*a3;
#pragma unroll
        for (int off = 16; off > 0; off >>= 1)
            s += __shfl_xor_sync(0xffffffffu, s, off);
        int lane = (threadIdx.y * DW_TX + threadIdx.x) & 31;
        if (lane == 0) {
            int t = o / C0, c = o % C0;
            atomicAdd(&normsq[(b * 2 + t) * C0 + c], s);
        }
    } else {
        int vc = o - 2 * C0;
        size_t off = ((size_t)b * C0 + vc) * HW + (size_t)y * WW + x0;
        bf16 h0 = __float2bfloat16(a0), h1 = __float2bfloat16(a1);
        bf16 h2 = __float2bfloat16(a2), h3 = __float2bfloat16(a3);
        bf16 l0 = __float2bfloat16(a0 - __bfloat162float(h0));
        bf16 l1 = __float2bfloat16(a1 - __bfloat162float(h1));
        bf16 l2 = __float2bfloat16(a2 - __bfloat162float(h2));
        bf16 l3 = __float2bfloat16(a3 - __bfloat162float(h3));
        __nv_bfloat162* hp = reinterpret_cast<__nv_bfloat162*>(vh + off);
        __nv_bfloat162* lp = reinterpret_cast<__nv_bfloat162*>(vl + off);
        hp[0] = __nv_bfloat162(h0, h1); hp[1] = __nv_bfloat162(h2, h3);
        lp[0] = __nv_bfloat162(l0, l1); lp[1] = __nv_bfloat162(l2, l3);
    }
}

// ---------------- zero attn + normsq ---------------------------------------
__global__ void zero_small(float* __restrict__ attn, float* __restrict__ normsq)
{
    int i = blockIdx.x * 256 + threadIdx.x;
    if (i < BATCH * NH * HD * HD) attn[i] = 0.f;
    if (i < BATCH * 2 * C0) normsq[i] = 0.f;
}

// ---------------- split-K q·k^T : 48x48 per (b,h), atomic accumulate -------
#define SPLITS 72
#define CHUNK (HW / SPLITS)   // 512
__global__ void __launch_bounds__(256) attn_qk(const float* __restrict__ qkv2,
                                               float* __restrict__ attn)
{
    const int split = blockIdx.x;
    const int bh = blockIdx.y;
    const int b = bh / NH, h = bh % NH;
    const float* qp = qkv2 + ((size_t)b * C3 +        h * HD) * HW;
    const float* kp = qkv2 + ((size_t)b * C3 + C0 +   h * HD) * HW;
    const int n0 = split * CHUNK;

    __shared__ float Qs[48][33];
    __shared__ float Ks[48][33];

    const int tid = threadIdx.x;
    const int tx = tid & 15;
    const int ty = tid >> 4;

    float acc[3][3] = {};

    for (int nb = 0; nb < CHUNK; nb += 32) {
#pragma unroll
        for (int r = 0; r < 6; r++) {
            int idx = tid + r * 256;
            int d = idx >> 5, nn = idx & 31;
            Qs[d][nn] = qp[(size_t)d * HW + n0 + nb + nn];
            Ks[d][nn] = kp[(size_t)d * HW + n0 + nb + nn];
        }
        __syncthreads();
#pragma unroll
        for (int kk = 0; kk < 32; kk++) {
            float a[3], bb[3];
#pragma unroll
            for (int i = 0; i < 3; i++) a[i]  = Qs[ty * 3 + i][kk];
#pragma unroll
            for (int j = 0; j < 3; j++) bb[j] = Ks[tx * 3 + j][kk];
#pragma unroll
            for (int i = 0; i < 3; i++)
#pragma unroll
                for (int j = 0; j < 3; j++) acc[i][j] += a[i] * bb[j];
        }
        __syncthreads();
    }

    float* ap = attn + (size_t)bh * HD * HD;
#pragma unroll
    for (int i = 0; i < 3; i++)
#pragma unroll
        for (int j = 0; j < 3; j++)
            atomicAdd(&ap[(ty * 3 + i) * HD + tx * 3 + j], acc[i][j]);
}

// ---------------- scale by norms + temperature, softmax over e -------------
__global__ void softmax_attn(float* __restrict__ attn, const float* __restrict__ normsq,
                             const float* __restrict__ logtemp)
{
    const int bh = blockIdx.x;
    const int b = bh / NH, h = bh % NH;
    const int d = threadIdx.x;
    if (d >= HD) return;

    float lt = logtemp[h];
    float temp = (lt > 20.f ? lt : log1pf(expf(lt))) + 1e-6f;

    const float* nq = normsq + (b * 2 + 0) * C0 + h * HD;
    const float* nk = normsq + (b * 2 + 1) * C0 + h * HD;
    float* row = attn + ((size_t)bh * HD + d) * HD;
    const float qn = fmaxf(sqrtf(nq[d]), 1e-12f);

    float vals[HD];
    float mx = -1e30f;
#pragma unroll
    for (int e = 0; e < HD; e++) {
        float kn = fmaxf(sqrtf(nk[e]), 1e-12f);
        float v = row[e] / (qn * kn) * temp;
        vals[e] = v;
        mx = fmaxf(mx, v);
    }
    float s = 0.f;
#pragma unroll
    for (int e = 0; e < HD; e++) {
        vals[e] = expf(vals[e] - mx);
        s += vals[e];
    }
    float inv = 1.f / s;
#pragma unroll
    for (int e = 0; e < HD; e++) row[e] = vals[e] * inv;
}

// ---------------- W2[b] = w_proj @ blockdiag(attn[b]) -> bf16 hi/lo --------
__global__ void build_w2(const float* __restrict__ wproj, const float* __restrict__ attn,
                         bf16* __restrict__ w2h, bf16* __restrict__ w2l)
{
    int idx = blockIdx.x * 256 + threadIdx.x;
    if (idx >= BATCH * C0 * C0) return;
    int cc = idx % C0;
    int o  = (idx / C0) % C0;
    int b  = idx / (C0 * C0);
    int h = cc / HD, e = cc % HD;
    float s = 0.f;
#pragma unroll
    for (int d = 0; d < HD; d++)
        s += wproj[o * C0 + h * HD + d] * attn[(((size_t)b * NH + h) * HD + d) * HD + e];
    bf16 hi = __float2bfloat16(s);
    bf16 lo = __float2bfloat16(s - __bfloat162float(hi));
    w2h[idx] = hi;
    w2l[idx] = lo;
}

// ---------------- launcher -------------------------------------------------
extern "C" void kernel_launch(void* const* d_in, const int* in_sizes, int n_in,
                              void* d_out, int out_size)
{
    const float* x      = (const float*)d_in[0];
    const float* w_qkv  = (const float*)d_in[1];
    const float* w_dw   = (const float*)d_in[2];
    const float* w_proj = (const float*)d_in[3];
    const float* ltemp  = (const float*)d_in[4];
    float* out = (float*)d_out;

    float *qkv1, *qkv2, *normsq, *attn;
    bf16 *xh, *xl, *vh, *vl, *wqh, *wql, *w2h, *w2l;
    cudaGetSymbolAddress((void**)&qkv1, g_qkv1);
    cudaGetSymbolAddress((void**)&qkv2, g_qkv2);
    cudaGetSymbolAddress((void**)&normsq, g_normsq);
    cudaGetSymbolAddress((void**)&attn, g_attn);
    cudaGetSymbolAddress((void**)&xh,  g_xh);
    cudaGetSymbolAddress((void**)&xl,  g_xl);
    cudaGetSymbolAddress((void**)&vh,  g_vh);
    cudaGetSymbolAddress((void**)&vl,  g_vl);
    cudaGetSymbolAddress((void**)&wqh, g_wqh);
    cudaGetSymbolAddress((void**)&wql, g_wql);
    cudaGetSymbolAddress((void**)&w2h, g_w2h);
    cudaGetSymbolAddress((void**)&w2l, g_w2l);

    cudaFuncSetAttribute(gemm_mma, cudaFuncAttributeMaxDynamicSharedMemorySize, SMEM_B);

    // 0) split x and w_qkv to bf16 hi/lo planes; zero accumulators
    {
        int total = BATCH * C0 * HW;
        split_batched<<<total / 4 / 256, 256>>>(x, (size_t)C0 * HW, C0 * HW, xh, xl, total);
        int wtot = C3 * C0;
        split_batched<<<(wtot / 4 + 255) / 256, 256>>>(w_qkv, wtot, wtot, wqh, wql, wtot);
        zero_small<<<(BATCH * NH * HD * HD + 255) / 256, 256>>>(attn, normsq);
    }
    // 1) qkv1 = w_qkv @ x
    {
        dim3 grid(HW / BN, (C3 + BM - 1) / BM, BATCH);
        gemm_mma<<<grid, 256, SMEM_B>>>(wqh, wql, xh, xl, qkv1,
                                        C3, HW, 0, (size_t)C0 * HW, (size_t)C3 * HW);
    }
    // 2) fused depthwise 3x3 + qk normsq + v split
    {
        dim3 grid(HH / DW_TY, BATCH * C3);
        dwconv_fused<<<grid, dim3(DW_TX, DW_TY)>>>(qkv1, w_dw, qkv2, vh, vl, normsq);
    }
    // 3) split-K q.k^T
    {
        dim3 grid(SPLITS, BATCH * NH);
        attn_qk<<<grid, 256>>>(qkv2, attn);
    }
    // 4) softmax
    softmax_attn<<<BATCH * NH, 64>>>(attn, normsq, ltemp);
    // 5) W2
    build_w2<<<(BATCH * C0 * C0 + 255) / 256, 256>>>(w_proj, attn, w2h, w2l);
    // 6) out = W2 @ v
    {
        dim3 grid(HW / BN, (C0 + BM - 1) / BM, BATCH);
        gemm_mma<<<grid, 256, SMEM_B>>>(w2h, w2l, vh, vl, out,
                                        C0, HW, (size_t)C0 * C0, (size_t)C0 * HW,
                                        (size_t)C0 * HW);
    }
}

// round 7
// speedup vs baseline: 2.6776x; 1.0764x over previous
#include <cuda_runtime.h>
#include <cuda_bf16.h>
#include <math.h>
#include <cstdint>

#define BATCH 2
#define C0 192
#define HH 192
#define WW 192
#define HW (HH*WW)          // 36864
#define C3 (3*C0)           // 576
#define NH 4
#define HD 48
#define KDIM 192

typedef __nv_bfloat16 bf16;

// ---------------- scratch (device globals; no allocs allowed) --------------
__device__ float g_qkv1[BATCH*C3*HW];      // after 1x1 conv
__device__ float g_normsq[BATCH*2*C0];     // [b][q|k][c]  sum of squares
__device__ float g_attn[BATCH*NH*HD*HD];   // raw dots -> softmaxed attn
__device__ bf16  g_xh[BATCH*C0*HW];        // x hi plane
__device__ bf16  g_xl[BATCH*C0*HW];        // x lo plane
__device__ bf16  g_vh[BATCH*C0*HW];        // v hi plane
__device__ bf16  g_vl[BATCH*C0*HW];        // v lo plane
__device__ bf16  g_qh[BATCH*C0*HW];        // q hi plane (post-dwconv)
__device__ bf16  g_ql[BATCH*C0*HW];        // q lo plane
__device__ bf16  g_kh[BATCH*C0*HW];        // k hi plane
__device__ bf16  g_kl[BATCH*C0*HW];        // k lo plane
__device__ bf16  g_wqh[C3*C0];             // w_qkv hi
__device__ bf16  g_wql[C3*C0];             // w_qkv lo
__device__ bf16  g_w2h[BATCH*C0*C0];       // w2 hi
__device__ bf16  g_w2l[BATCH*C0*C0];       // w2 lo

// ======================= small helpers =====================================
__device__ __forceinline__ uint32_t smem_u32(const void* p) {
    uint32_t a;
    asm("{ .reg .u64 t; cvta.to.shared.u64 t, %1; cvt.u32.u64 %0, t; }"
        : "=r"(a) : "l"(p));
    return a;
}
__device__ __forceinline__ void ldsm4(uint32_t addr, uint32_t* r) {
    asm volatile("ldmatrix.sync.aligned.m8n8.x4.shared.b16 {%0,%1,%2,%3}, [%4];"
        : "=r"(r[0]), "=r"(r[1]), "=r"(r[2]), "=r"(r[3]) : "r"(addr));
}
__device__ __forceinline__ void ldsm4t(uint32_t addr, uint32_t* r) {
    asm volatile("ldmatrix.sync.aligned.m8n8.x4.trans.shared.b16 {%0,%1,%2,%3}, [%4];"
        : "=r"(r[0]), "=r"(r[1]), "=r"(r[2]), "=r"(r[3]) : "r"(addr));
}
__device__ __forceinline__ void mma16816(float* d, const uint32_t* a, const uint32_t* b) {
    asm volatile(
        "mma.sync.aligned.m16n8k16.row.col.f32.bf16.bf16.f32 "
        "{%0,%1,%2,%3}, {%4,%5,%6,%7}, {%8,%9}, {%0,%1,%2,%3};"
        : "+f"(d[0]), "+f"(d[1]), "+f"(d[2]), "+f"(d[3])
        : "r"(a[0]), "r"(a[1]), "r"(a[2]), "r"(a[3]), "r"(b[0]), "r"(b[1]));
}
__device__ __forceinline__ void cpa16(uint32_t dst, const void* src, int bytes) {
    asm volatile("cp.async.cg.shared.global [%0], [%1], 16, %2;"
        :: "r"(dst), "l"(src), "r"(bytes));
}
#define CP_COMMIT() asm volatile("cp.async.commit_group;")
#define CP_WAIT(n)  asm volatile("cp.async.wait_group %0;" :: "n"(n))

// ======================= split-bf16 conversion =============================
__global__ void __launch_bounds__(256) split_batched(
    const float* __restrict__ src, size_t bstride, int per_batch,
    bf16* __restrict__ h, bf16* __restrict__ l, int total)
{
    int i4 = (blockIdx.x * 256 + threadIdx.x) * 4;
    if (i4 >= total) return;
    int b = i4 / per_batch;
    int rem = i4 - b * per_batch;
    float4 v = *reinterpret_cast<const float4*>(src + (size_t)b * bstride + rem);
    bf16 h0 = __float2bfloat16(v.x), h1 = __float2bfloat16(v.y);
    bf16 h2 = __float2bfloat16(v.z), h3 = __float2bfloat16(v.w);
    bf16 l0 = __float2bfloat16(v.x - __bfloat162float(h0));
    bf16 l1 = __float2bfloat16(v.y - __bfloat162float(h1));
    bf16 l2 = __float2bfloat16(v.z - __bfloat162float(h2));
    bf16 l3 = __float2bfloat16(v.w - __bfloat162float(h3));
    __nv_bfloat162* hp = reinterpret_cast<__nv_bfloat162*>(h + i4);
    __nv_bfloat162* lp = reinterpret_cast<__nv_bfloat162*>(l + i4);
    hp[0] = __nv_bfloat162(h0, h1); hp[1] = __nv_bfloat162(h2, h3);
    lp[0] = __nv_bfloat162(l0, l1); lp[1] = __nv_bfloat162(l2, l3);
}

// ======================= tensor-core GEMM (mma.sync bf16 split) ============
#define BM 128
#define BN 128
#define BK 32
#define NCHUNK (KDIM/BK)     // 6
#define SA 40
#define SB 136
#define A_PLANE_B (BM*SA*2)
#define B_PLANE_B (BK*SB*2)
#define OFF_AH 0
#define OFF_AL (A_PLANE_B)
#define OFF_BH (2*A_PLANE_B)
#define OFF_BL (2*A_PLANE_B + B_PLANE_B)
#define BUF_B  (2*A_PLANE_B + 2*B_PLANE_B)   // 37888
#define NSTAGE 3
#define SMEM_B (NSTAGE*BUF_B)                // 113664

__global__ void __launch_bounds__(256) gemm_mma(
    const bf16* __restrict__ Ah, const bf16* __restrict__ Al,
    const bf16* __restrict__ Bh, const bf16* __restrict__ Bl,
    float* __restrict__ C, int Mreal, int ldc,
    size_t sAb, size_t sBb, size_t sCb)
{
    extern __shared__ char smem[];
    const uint32_t sb = smem_u32(smem);
    const int tid  = threadIdx.x;
    const int wid  = tid >> 5;
    const int lane = tid & 31;
    const int warp_m = wid & 1;
    const int warp_n = wid >> 1;

    const int bz = blockIdx.z;
    const bf16* Ahb = Ah + bz * sAb;
    const bf16* Alb = Al + bz * sAb;
    const bf16* Bhb = Bh + bz * sBb;
    const bf16* Blb = Bl + bz * sBb;
    float*      Cb  = C  + bz * sCb;

    const int m0 = blockIdx.y * BM;
    const int n0 = blockIdx.x * BN;

    float acc[4][4][4];
#pragma unroll
    for (int i = 0; i < 4; i++)
#pragma unroll
        for (int j = 0; j < 4; j++)
#pragma unroll
            for (int q = 0; q < 4; q++) acc[i][j][q] = 0.f;

    auto issue = [&](int kc, int buf) {
        uint32_t base = sb + buf * BUF_B;
#pragma unroll
        for (int r = 0; r < 2; r++) {
            int c = tid * 2 + r;
            int row = c >> 2, seg = c & 3;
            int grow = m0 + row;
            int ok = (grow < Mreal) ? 16 : 0;
            int gr = (grow < Mreal) ? grow : 0;
            size_t go = (size_t)gr * KDIM + kc + seg * 8;
            uint32_t so = (uint32_t)(row * SA + seg * 8) * 2;
            cpa16(base + OFF_AH + so, Ahb + go, ok);
            cpa16(base + OFF_AL + so, Alb + go, ok);
        }
#pragma unroll
        for (int r = 0; r < 2; r++) {
            int c = tid * 2 + r;
            int row = c >> 4, seg = c & 15;
            size_t go = (size_t)(kc + row) * HW + n0 + seg * 8;
            uint32_t so = (uint32_t)(row * SB + seg * 8) * 2;
            cpa16(base + OFF_BH + so, Bhb + go, 16);
            cpa16(base + OFF_BL + so, Blb + go, 16);
        }
        CP_COMMIT();
    };

    issue(0, 0);
    issue(BK, 1);

    const int arow = warp_m * 64 + (lane & 15);
    const int acolb = (lane >> 4) * 8;
    const int brow = (lane & 7) + ((lane >> 3) & 1) * 8;
    const int bcol = warp_n * 32 + ((lane >> 4) & 1) * 8;

    int buf = 0;
    for (int ch = 0; ch < NCHUNK; ch++) {
        if (ch < NCHUNK - 1) { CP_WAIT(1); } else { CP_WAIT(0); }
        __syncthreads();
        if (ch < NCHUNK - 2) {
            int nb = buf + 2; if (nb >= NSTAGE) nb -= NSTAGE;
            issue((ch + 2) * BK, nb);
        }

        uint32_t base = sb + buf * BUF_B;
#pragma unroll
        for (int ks = 0; ks < 2; ks++) {
            uint32_t ah[4][4], al[4][4], bh[2][4], bl[2][4];
            int acol = ks * 16 + acolb;
#pragma unroll
            for (int mt = 0; mt < 4; mt++) {
                uint32_t ao = (uint32_t)((arow + mt * 16) * SA + acol) * 2;
                ldsm4(base + OFF_AH + ao, ah[mt]);
                ldsm4(base + OFF_AL + ao, al[mt]);
            }
            int krow = ks * 16 + brow;
#pragma unroll
            for (int p = 0; p < 2; p++) {
                uint32_t bo = (uint32_t)(krow * SB + bcol + p * 16) * 2;
                ldsm4t(base + OFF_BH + bo, bh[p]);
                ldsm4t(base + OFF_BL + bo, bl[p]);
            }
#pragma unroll
            for (int mt = 0; mt < 4; mt++)
#pragma unroll
                for (int nt = 0; nt < 4; nt++) {
                    const uint32_t* bfh = &bh[nt >> 1][(nt & 1) * 2];
                    const uint32_t* bfl = &bl[nt >> 1][(nt & 1) * 2];
                    mma16816(acc[mt][nt], ah[mt], bfh);
                    mma16816(acc[mt][nt], ah[mt], bfl);
                    mma16816(acc[mt][nt], al[mt], bfh);
                }
        }
        buf++; if (buf >= NSTAGE) buf = 0;
    }

    const int erow = lane >> 2;
    const int ecol = (lane & 3) * 2;
#pragma unroll
    for (int mt = 0; mt < 4; mt++) {
        int r0 = m0 + warp_m * 64 + mt * 16 + erow;
        int r1 = r0 + 8;
#pragma unroll
        for (int nt = 0; nt < 4; nt++) {
            int cc = n0 + warp_n * 32 + nt * 8 + ecol;
            if (r0 < Mreal)
                *reinterpret_cast<float2*>(Cb + (size_t)r0 * ldc + cc) =
                    make_float2(acc[mt][nt][0], acc[mt][nt][1]);
            if (r1 < Mreal)
                *reinterpret_cast<float2*>(Cb + (size_t)r1 * ldc + cc) =
                    make_float2(acc[mt][nt][2], acc[mt][nt][3]);
        }
    }
}

// ============ fused depthwise 3x3 + qk planes + normsq + v planes ==========
#define DW_TX 48
#define DW_TY 8
__global__ void __launch_bounds__(DW_TX*DW_TY) dwconv_fused(
    const float* __restrict__ in, const float* __restrict__ wdw,
    bf16* __restrict__ qh, bf16* __restrict__ ql,
    bf16* __restrict__ kh, bf16* __restrict__ kl,
    bf16* __restrict__ vh, bf16* __restrict__ vl,
    float* __restrict__ normsq)
{
    const int bc = blockIdx.y;           // b*C3 + o
    const int b  = bc / C3;
    const int o  = bc % C3;
    const float* ip = in + (size_t)bc * HW;

    float w[9];
#pragma unroll
    for (int i = 0; i < 9; i++) w[i] = __ldg(wdw + o * 9 + i);

    const int y  = blockIdx.x * DW_TY + threadIdx.y;
    const int x0 = threadIdx.x * 4;

    float a0 = 0.f, a1 = 0.f, a2 = 0.f, a3 = 0.f;
#pragma unroll
    for (int dy = 0; dy < 3; dy++) {
        int yy = y + dy - 1;
        if (yy < 0 || yy >= HH) continue;
        const float* rp = ip + (size_t)yy * WW;
        float4 c  = *reinterpret_cast<const float4*>(rp + x0);
        float lft = (x0 > 0)       ? rp[x0 - 1] : 0.f;
        float rgt = (x0 + 4 < WW)  ? rp[x0 + 4] : 0.f;
        float w0 = w[dy*3], w1 = w[dy*3+1], w2 = w[dy*3+2];
        a0 += w0*lft + w1*c.x + w2*c.y;
        a1 += w0*c.x + w1*c.y + w2*c.z;
        a2 += w0*c.y + w1*c.z + w2*c.w;
        a3 += w0*c.z + w1*c.w + w2*rgt;
    }

    // hi/lo split of the 4 outputs (used by all branches)
    bf16 h0 = __float2bfloat16(a0), h1 = __float2bfloat16(a1);
    bf16 h2 = __float2bfloat16(a2), h3 = __float2bfloat16(a3);
    bf16 l0 = __float2bfloat16(a0 - __bfloat162float(h0));
    bf16 l1 = __float2bfloat16(a1 - __bfloat162float(h1));
    bf16 l2 = __float2bfloat16(a2 - __bfloat162float(h2));
    bf16 l3 = __float2bfloat16(a3 - __bfloat162float(h3));

    const int t = o / C0;                // 0=q, 1=k, 2=v
    const int c = o % C0;
    size_t off = ((size_t)b * C0 + c) * HW + (size_t)y * WW + x0;
    bf16* hp;
    bf16* lp;
    if (t == 0)      { hp = qh; lp = ql; }
    else if (t == 1) { hp = kh; lp = kl; }
    else             { hp = vh; lp = vl; }
    __nv_bfloat162* hpp = reinterpret_cast<__nv_bfloat162*>(hp + off);
    __nv_bfloat162* lpp = reinterpret_cast<__nv_bfloat162*>(lp + off);
    hpp[0] = __nv_bfloat162(h0, h1); hpp[1] = __nv_bfloat162(h2, h3);
    lpp[0] = __nv_bfloat162(l0, l1); lpp[1] = __nv_bfloat162(l2, l3);

    if (t < 2) {
        // q/k: accumulate sum of squares (exact fp32)
        float s = a0*a0 + a1*a1 + a2*a2 + a3*a3;
#pragma unroll
        for (int offm = 16; offm > 0; offm >>= 1)
            s += __shfl_xor_sync(0xffffffffu, s, offm);
        int lane = (threadIdx.y * DW_TX + threadIdx.x) & 31;
        if (lane == 0)
            atomicAdd(&normsq[(b * 2 + t) * C0 + c], s);
    }
}

// ---------------- zero attn + normsq ---------------------------------------
__global__ void zero_small(float* __restrict__ attn, float* __restrict__ normsq)
{
    int i = blockIdx.x * 256 + threadIdx.x;
    if (i < BATCH * NH * HD * HD) attn[i] = 0.f;
    if (i < BATCH * 2 * C0) normsq[i] = 0.f;
}

// ---------------- tensor-core q·k^T ----------------------------------------
// grid (18, 8bh); block 256 (8 warps, each owns a k16 slice of a 128-k
// subchunk). q,k bf16 hi/lo planes; 3-pass split mma. smem-reduce + atomics.
#define AT_NSPL 18
#define AT_KBLK (HW/AT_NSPL)   // 2048
#define AT_SK 128
#define AT_SUB (AT_KBLK/AT_SK) // 16
#define AT_SROW 136            // padded row (elems)
#define AT_PLANE (48*AT_SROW*2)  // 13056 B
#define AT_STAGE (4*AT_PLANE)    // 52224 B
#define AT_SMEM (2*AT_STAGE)     // 104448 B

__global__ void __launch_bounds__(256) attn_mma(
    const bf16* __restrict__ qh, const bf16* __restrict__ ql,
    const bf16* __restrict__ kh, const bf16* __restrict__ kl,
    float* __restrict__ attn)
{
    extern __shared__ char smem[];
    const uint32_t sb = smem_u32(smem);
    const int tid  = threadIdx.x;
    const int wid  = tid >> 5;
    const int lane = tid & 31;

    const int bh = blockIdx.y;
    const int b = bh / NH, h = bh % NH;
    const size_t rowbase = ((size_t)b * C0 + h * HD) * HW;
    const bf16* pl[4] = { qh + rowbase, ql + rowbase, kh + rowbase, kl + rowbase };
    const size_t kblk0 = (size_t)blockIdx.x * AT_KBLK;

    float acc[3][6][4];
#pragma unroll
    for (int i = 0; i < 3; i++)
#pragma unroll
        for (int j = 0; j < 6; j++)
#pragma unroll
            for (int q = 0; q < 4; q++) acc[i][j][q] = 0.f;

    auto fill = [&](int sub, int stg) {
        uint32_t base = sb + stg * AT_STAGE;
        size_t k0 = kblk0 + (size_t)sub * AT_SK;
#pragma unroll
        for (int p = 0; p < 4; p++) {
#pragma unroll
            for (int r = 0; r < 3; r++) {
                int cc = tid + r * 256;           // 0..767
                int row = cc >> 4, seg = cc & 15;
                cpa16(base + p * AT_PLANE + (uint32_t)(row * AT_SROW + seg * 8) * 2,
                      pl[p] + (size_t)row * HW + k0 + seg * 8, 16);
            }
        }
        CP_COMMIT();
    };

    fill(0, 0);

    const int kofs = wid * 16;
    // A (q) ldsm addressing
    const int a_r = lane & 15;
    const int a_c = kofs + (lane >> 4) * 8;
    // B (k) ldsm addressing (non-trans, [n][k] storage)
    const int b_r = (lane & 7) + ((lane >> 4) & 1) * 8;
    const int b_c = kofs + ((lane >> 3) & 1) * 8;

    for (int sub = 0; sub < AT_SUB; sub++) {
        CP_WAIT(0);
        __syncthreads();
        if (sub < AT_SUB - 1) fill(sub + 1, (sub + 1) & 1);

        uint32_t base = sb + (sub & 1) * AT_STAGE;
        uint32_t qhf[3][4], qlf[3][4], khf[3][4], klf[3][4];
#pragma unroll
        for (int mt = 0; mt < 3; mt++) {
            uint32_t ao = (uint32_t)((mt * 16 + a_r) * AT_SROW + a_c) * 2;
            ldsm4(base + 0 * AT_PLANE + ao, qhf[mt]);
            ldsm4(base + 1 * AT_PLANE + ao, qlf[mt]);
        }
#pragma unroll
        for (int nt2 = 0; nt2 < 3; nt2++) {
            uint32_t bo = (uint32_t)((nt2 * 16 + b_r) * AT_SROW + b_c) * 2;
            ldsm4(base + 2 * AT_PLANE + bo, khf[nt2]);
            ldsm4(base + 3 * AT_PLANE + bo, klf[nt2]);
        }
#pragma unroll
        for (int mt = 0; mt < 3; mt++)
#pragma unroll
            for (int nt = 0; nt < 6; nt++) {
                const uint32_t* bfh = &khf[nt >> 1][(nt & 1) * 2];
                const uint32_t* bfl = &klf[nt >> 1][(nt & 1) * 2];
                mma16816(acc[mt][nt], qhf[mt], bfh);
                mma16816(acc[mt][nt], qhf[mt], bfl);
                mma16816(acc[mt][nt], qlf[mt], bfh);
            }
        __syncthreads();   // all warps done with this stage before refill
    }

    // ---- reduce across warps in smem, then atomics to global ----
    float* red = reinterpret_cast<float*>(smem);   // [48][49]
    for (int i = tid; i < 48 * 49; i += 256) red[i] = 0.f;
    __syncthreads();
    const int erow = lane >> 2;
    const int ecol = (lane & 3) * 2;
#pragma unroll
    for (int mt = 0; mt < 3; mt++) {
        int r0 = mt * 16 + erow;
#pragma unroll
        for (int nt = 0; nt < 6; nt++) {
            int cc = nt * 8 + ecol;
            atomicAdd(&red[r0 * 49 + cc],       acc[mt][nt][0]);
            atomicAdd(&red[r0 * 49 + cc + 1],   acc[mt][nt][1]);
            atomicAdd(&red[(r0 + 8) * 49 + cc],     acc[mt][nt][2]);
            atomicAdd(&red[(r0 + 8) * 49 + cc + 1], acc[mt][nt][3]);
        }
    }
    __syncthreads();
    float* ap = attn + (size_t)bh * HD * HD;
    for (int i = tid; i < HD * HD; i += 256) {
        int r = i / HD, cl = i % HD;
        atomicAdd(&ap[i], red[r * 49 + cl]);
    }
}

// ---------------- scale by norms + temperature, softmax over e -------------
__global__ void softmax_attn(float* __restrict__ attn, const float* __restrict__ normsq,
                             const float* __restrict__ logtemp)
{
    const int bh = blockIdx.x;
    const int b = bh / NH, h = bh % NH;
    const int d = threadIdx.x;
    if (d >= HD) return;

    float lt = logtemp[h];
    float temp = (lt > 20.f ? lt : log1pf(expf(lt))) + 1e-6f;

    const float* nq = normsq + (b * 2 + 0) * C0 + h * HD;
    const float* nk = normsq + (b * 2 + 1) * C0 + h * HD;
    float* row = attn + ((size_t)bh * HD + d) * HD;
    const float qn = fmaxf(sqrtf(nq[d]), 1e-12f);

    float vals[HD];
    float mx = -1e30f;
#pragma unroll
    for (int e = 0; e < HD; e++) {
        float kn = fmaxf(sqrtf(nk[e]), 1e-12f);
        float v = row[e] / (qn * kn) * temp;
        vals[e] = v;
        mx = fmaxf(mx, v);
    }
    float s = 0.f;
#pragma unroll
    for (int e = 0; e < HD; e++) {
        vals[e] = expf(vals[e] - mx);
        s += vals[e];
    }
    float inv = 1.f / s;
#pragma unroll
    for (int e = 0; e < HD; e++) row[e] = vals[e] * inv;
}

// ---------------- W2[b] = w_proj @ blockdiag(attn[b]) -> bf16 hi/lo --------
__global__ void build_w2(const float* __restrict__ wproj, const float* __restrict__ attn,
                         bf16* __restrict__ w2h, bf16* __restrict__ w2l)
{
    int idx = blockIdx.x * 256 + threadIdx.x;
    if (idx >= BATCH * C0 * C0) return;
    int cc = idx % C0;
    int o  = (idx / C0) % C0;
    int b  = idx / (C0 * C0);
    int h = cc / HD, e = cc % HD;
    float s = 0.f;
#pragma unroll
    for (int d = 0; d < HD; d++)
        s += wproj[o * C0 + h * HD + d] * attn[(((size_t)b * NH + h) * HD + d) * HD + e];
    bf16 hi = __float2bfloat16(s);
    bf16 lo = __float2bfloat16(s - __bfloat162float(hi));
    w2h[idx] = hi;
    w2l[idx] = lo;
}

// ---------------- launcher -------------------------------------------------
extern "C" void kernel_launch(void* const* d_in, const int* in_sizes, int n_in,
                              void* d_out, int out_size)
{
    const float* x      = (const float*)d_in[0];
    const float* w_qkv  = (const float*)d_in[1];
    const float* w_dw   = (const float*)d_in[2];
    const float* w_proj = (const float*)d_in[3];
    const float* ltemp  = (const float*)d_in[4];
    float* out = (float*)d_out;

    float *qkv1, *normsq, *attn;
    bf16 *xh, *xl, *vh, *vl, *qh, *ql, *kh, *kl, *wqh, *wql, *w2h, *w2l;
    cudaGetSymbolAddress((void**)&qkv1, g_qkv1);
    cudaGetSymbolAddress((void**)&normsq, g_normsq);
    cudaGetSymbolAddress((void**)&attn, g_attn);
    cudaGetSymbolAddress((void**)&xh,  g_xh);
    cudaGetSymbolAddress((void**)&xl,  g_xl);
    cudaGetSymbolAddress((void**)&vh,  g_vh);
    cudaGetSymbolAddress((void**)&vl,  g_vl);
    cudaGetSymbolAddress((void**)&qh,  g_qh);
    cudaGetSymbolAddress((void**)&ql,  g_ql);
    cudaGetSymbolAddress((void**)&kh,  g_kh);
    cudaGetSymbolAddress((void**)&kl,  g_kl);
    cudaGetSymbolAddress((void**)&wqh, g_wqh);
    cudaGetSymbolAddress((void**)&wql, g_wql);
    cudaGetSymbolAddress((void**)&w2h, g_w2h);
    cudaGetSymbolAddress((void**)&w2l, g_w2l);

    cudaFuncSetAttribute(gemm_mma, cudaFuncAttributeMaxDynamicSharedMemorySize, SMEM_B);
    cudaFuncSetAttribute(attn_mma, cudaFuncAttributeMaxDynamicSharedMemorySize, AT_SMEM);

    // 0) split x and w_qkv to bf16 hi/lo planes; zero accumulators
    {
        int total = BATCH * C0 * HW;
        split_batched<<<total / 4 / 256, 256>>>(x, (size_t)C0 * HW, C0 * HW, xh, xl, total);
        int wtot = C3 * C0;
        split_batched<<<(wtot / 4 + 255) / 256, 256>>>(w_qkv, wtot, wtot, wqh, wql, wtot);
        zero_small<<<(BATCH * NH * HD * HD + 255) / 256, 256>>>(attn, normsq);
    }
    // 1) qkv1 = w_qkv @ x
    {
        dim3 grid(HW / BN, (C3 + BM - 1) / BM, BATCH);
        gemm_mma<<<grid, 256, SMEM_B>>>(wqh, wql, xh, xl, qkv1,
                                        C3, HW, 0, (size_t)C0 * HW, (size_t)C3 * HW);
    }
    // 2) fused depthwise 3x3 -> q,k,v hi/lo planes + qk normsq
    {
        dim3 grid(HH / DW_TY, BATCH * C3);
        dwconv_fused<<<grid, dim3(DW_TX, DW_TY)>>>(qkv1, w_dw, qh, ql, kh, kl,
                                                   vh, vl, normsq);
    }
    // 3) tensor-core q.k^T
    {
        dim3 grid(AT_NSPL, BATCH * NH);
        attn_mma<<<grid, 256, AT_SMEM>>>(qh, ql, kh, kl, attn);
    }
    // 4) softmax
    softmax_attn<<<BATCH * NH, 64>>>(attn, normsq, ltemp);
    // 5) W2
    build_w2<<<(BATCH * C0 * C0 + 255) / 256, 256>>>(w_proj, attn, w2h, w2l);
    // 6) out = W2 @ v
    {
        dim3 grid(HW / BN, (C0 + BM - 1) / BM, BATCH);
        gemm_mma<<<grid, 256, SMEM_B>>>(w2h, w2l, vh, vl, out,
                                        C0, HW, (size_t)C0 * C0, (size_t)C0 * HW,
                                        (size_t)C0 * HW);
    }
}

// round 8
// speedup vs baseline: 3.1833x; 1.1889x over previous
#include <cuda_runtime.h>
#include <cuda_bf16.h>
#include <math.h>
#include <cstdint>

#define BATCH 2
#define C0 192
#define HH 192
#define WW 192
#define HW (HH*WW)          // 36864
#define C3 (3*C0)           // 576
#define NH 4
#define HD 48
#define KDIM 192

typedef __nv_bfloat16 bf16;

// ---------------- scratch (device globals; no allocs allowed) --------------
__device__ float g_qkv1[BATCH*C3*HW];      // after 1x1 conv
__device__ float g_normsq[BATCH*2*C0];     // [b][q|k][c]  sum of squares
__device__ float g_attn[BATCH*NH*HD*HD];   // raw dots -> softmaxed attn
__device__ bf16  g_xh[BATCH*C0*HW];        // x hi plane
__device__ bf16  g_xl[BATCH*C0*HW];        // x lo plane
__device__ bf16  g_vh[BATCH*C0*HW];        // v hi plane
__device__ bf16  g_vl[BATCH*C0*HW];        // v lo plane
__device__ bf16  g_qh[BATCH*C0*HW];        // q hi plane (post-dwconv)
__device__ bf16  g_ql[BATCH*C0*HW];        // q lo plane
__device__ bf16  g_kh[BATCH*C0*HW];        // k hi plane
__device__ bf16  g_kl[BATCH*C0*HW];        // k lo plane
__device__ bf16  g_wqh[C3*C0];             // w_qkv hi
__device__ bf16  g_wql[C3*C0];             // w_qkv lo
__device__ bf16  g_w2h[BATCH*C0*C0];       // w2 hi
__device__ bf16  g_w2l[BATCH*C0*C0];       // w2 lo

// ======================= small helpers =====================================
__device__ __forceinline__ uint32_t smem_u32(const void* p) {
    uint32_t a;
    asm("{ .reg .u64 t; cvta.to.shared.u64 t, %1; cvt.u32.u64 %0, t; }"
        : "=r"(a) : "l"(p));
    return a;
}
__device__ __forceinline__ void ldsm4(uint32_t addr, uint32_t* r) {
    asm volatile("ldmatrix.sync.aligned.m8n8.x4.shared.b16 {%0,%1,%2,%3}, [%4];"
        : "=r"(r[0]), "=r"(r[1]), "=r"(r[2]), "=r"(r[3]) : "r"(addr));
}
__device__ __forceinline__ void ldsm4t(uint32_t addr, uint32_t* r) {
    asm volatile("ldmatrix.sync.aligned.m8n8.x4.trans.shared.b16 {%0,%1,%2,%3}, [%4];"
        : "=r"(r[0]), "=r"(r[1]), "=r"(r[2]), "=r"(r[3]) : "r"(addr));
}
__device__ __forceinline__ void mma16816(float* d, const uint32_t* a, const uint32_t* b) {
    asm volatile(
        "mma.sync.aligned.m16n8k16.row.col.f32.bf16.bf16.f32 "
        "{%0,%1,%2,%3}, {%4,%5,%6,%7}, {%8,%9}, {%0,%1,%2,%3};"
        : "+f"(d[0]), "+f"(d[1]), "+f"(d[2]), "+f"(d[3])
        : "r"(a[0]), "r"(a[1]), "r"(a[2]), "r"(a[3]), "r"(b[0]), "r"(b[1]));
}
__device__ __forceinline__ void cpa16(uint32_t dst, const void* src, int bytes) {
    asm volatile("cp.async.cg.shared.global [%0], [%1], 16, %2;"
        :: "r"(dst), "l"(src), "r"(bytes));
}
#define CP_COMMIT() asm volatile("cp.async.commit_group;")
#define CP_WAIT(n)  asm volatile("cp.async.wait_group %0;" :: "n"(n))

// ======================= split-bf16 conversion =============================
__global__ void __launch_bounds__(256) split_batched(
    const float* __restrict__ src, size_t bstride, int per_batch,
    bf16* __restrict__ h, bf16* __restrict__ l, int total)
{
    int i4 = (blockIdx.x * 256 + threadIdx.x) * 4;
    if (i4 >= total) return;
    int b = i4 / per_batch;
    int rem = i4 - b * per_batch;
    float4 v = *reinterpret_cast<const float4*>(src + (size_t)b * bstride + rem);
    bf16 h0 = __float2bfloat16(v.x), h1 = __float2bfloat16(v.y);
    bf16 h2 = __float2bfloat16(v.z), h3 = __float2bfloat16(v.w);
    bf16 l0 = __float2bfloat16(v.x - __bfloat162float(h0));
    bf16 l1 = __float2bfloat16(v.y - __bfloat162float(h1));
    bf16 l2 = __float2bfloat16(v.z - __bfloat162float(h2));
    bf16 l3 = __float2bfloat16(v.w - __bfloat162float(h3));
    __nv_bfloat162* hp = reinterpret_cast<__nv_bfloat162*>(h + i4);
    __nv_bfloat162* lp = reinterpret_cast<__nv_bfloat162*>(l + i4);
    hp[0] = __nv_bfloat162(h0, h1); hp[1] = __nv_bfloat162(h2, h3);
    lp[0] = __nv_bfloat162(l0, l1); lp[1] = __nv_bfloat162(l2, l3);
}

// ======================= tensor-core GEMM (mma.sync bf16 split) ============
#define BM 128
#define BN 128
#define BK 32
#define NCHUNK (KDIM/BK)     // 6
#define SA 40
#define SB 136
#define A_PLANE_B (BM*SA*2)
#define B_PLANE_B (BK*SB*2)
#define OFF_AH 0
#define OFF_AL (A_PLANE_B)
#define OFF_BH (2*A_PLANE_B)
#define OFF_BL (2*A_PLANE_B + B_PLANE_B)
#define BUF_B  (2*A_PLANE_B + 2*B_PLANE_B)   // 37888
#define NSTAGE 3
#define SMEM_B (NSTAGE*BUF_B)                // 113664

__global__ void __launch_bounds__(256) gemm_mma(
    const bf16* __restrict__ Ah, const bf16* __restrict__ Al,
    const bf16* __restrict__ Bh, const bf16* __restrict__ Bl,
    float* __restrict__ C, int Mreal, int ldc,
    size_t sAb, size_t sBb, size_t sCb)
{
    extern __shared__ char smem[];
    const uint32_t sb = smem_u32(smem);
    const int tid  = threadIdx.x;
    const int wid  = tid >> 5;
    const int lane = tid & 31;
    const int warp_m = wid & 1;
    const int warp_n = wid >> 1;

    const int bz = blockIdx.z;
    const bf16* Ahb = Ah + bz * sAb;
    const bf16* Alb = Al + bz * sAb;
    const bf16* Bhb = Bh + bz * sBb;
    const bf16* Blb = Bl + bz * sBb;
    float*      Cb  = C  + bz * sCb;

    const int m0 = blockIdx.y * BM;
    const int n0 = blockIdx.x * BN;
    // warp-uniform: does this warp's 64-row slice contain any valid rows?
    const bool mactive = (m0 + warp_m * 64) < Mreal;

    float acc[4][4][4];
#pragma unroll
    for (int i = 0; i < 4; i++)
#pragma unroll
        for (int j = 0; j < 4; j++)
#pragma unroll
            for (int q = 0; q < 4; q++) acc[i][j][q] = 0.f;

    auto issue = [&](int kc, int buf) {
        uint32_t base = sb + buf * BUF_B;
#pragma unroll
        for (int r = 0; r < 2; r++) {
            int c = tid * 2 + r;
            int row = c >> 2, seg = c & 3;
            int grow = m0 + row;
            int ok = (grow < Mreal) ? 16 : 0;
            int gr = (grow < Mreal) ? grow : 0;
            size_t go = (size_t)gr * KDIM + kc + seg * 8;
            uint32_t so = (uint32_t)(row * SA + seg * 8) * 2;
            cpa16(base + OFF_AH + so, Ahb + go, ok);
            cpa16(base + OFF_AL + so, Alb + go, ok);
        }
#pragma unroll
        for (int r = 0; r < 2; r++) {
            int c = tid * 2 + r;
            int row = c >> 4, seg = c & 15;
            size_t go = (size_t)(kc + row) * HW + n0 + seg * 8;
            uint32_t so = (uint32_t)(row * SB + seg * 8) * 2;
            cpa16(base + OFF_BH + so, Bhb + go, 16);
            cpa16(base + OFF_BL + so, Blb + go, 16);
        }
        CP_COMMIT();
    };

    issue(0, 0);
    issue(BK, 1);

    const int arow = warp_m * 64 + (lane & 15);
    const int acolb = (lane >> 4) * 8;
    const int brow = (lane & 7) + ((lane >> 3) & 1) * 8;
    const int bcol = warp_n * 32 + ((lane >> 4) & 1) * 8;

    int buf = 0;
    for (int ch = 0; ch < NCHUNK; ch++) {
        if (ch < NCHUNK - 1) { CP_WAIT(1); } else { CP_WAIT(0); }
        __syncthreads();
        if (ch < NCHUNK - 2) {
            int nb = buf + 2; if (nb >= NSTAGE) nb -= NSTAGE;
            issue((ch + 2) * BK, nb);
        }

        if (mactive) {
            uint32_t base = sb + buf * BUF_B;
#pragma unroll
            for (int ks = 0; ks < 2; ks++) {
                uint32_t ah[4][4], al[4][4], bh[2][4], bl[2][4];
                int acol = ks * 16 + acolb;
#pragma unroll
                for (int mt = 0; mt < 4; mt++) {
                    uint32_t ao = (uint32_t)((arow + mt * 16) * SA + acol) * 2;
                    ldsm4(base + OFF_AH + ao, ah[mt]);
                    ldsm4(base + OFF_AL + ao, al[mt]);
                }
                int krow = ks * 16 + brow;
#pragma unroll
                for (int p = 0; p < 2; p++) {
                    uint32_t bo = (uint32_t)(krow * SB + bcol + p * 16) * 2;
                    ldsm4t(base + OFF_BH + bo, bh[p]);
                    ldsm4t(base + OFF_BL + bo, bl[p]);
                }
#pragma unroll
                for (int mt = 0; mt < 4; mt++)
#pragma unroll
                    for (int nt = 0; nt < 4; nt++) {
                        const uint32_t* bfh = &bh[nt >> 1][(nt & 1) * 2];
                        const uint32_t* bfl = &bl[nt >> 1][(nt & 1) * 2];
                        mma16816(acc[mt][nt], ah[mt], bfh);
                        mma16816(acc[mt][nt], ah[mt], bfl);
                        mma16816(acc[mt][nt], al[mt], bfh);
                    }
            }
        }
        buf++; if (buf >= NSTAGE) buf = 0;
    }

    const int erow = lane >> 2;
    const int ecol = (lane & 3) * 2;
    if (mactive) {
#pragma unroll
        for (int mt = 0; mt < 4; mt++) {
            int r0 = m0 + warp_m * 64 + mt * 16 + erow;
            int r1 = r0 + 8;
#pragma unroll
            for (int nt = 0; nt < 4; nt++) {
                int cc = n0 + warp_n * 32 + nt * 8 + ecol;
                if (r0 < Mreal)
                    *reinterpret_cast<float2*>(Cb + (size_t)r0 * ldc + cc) =
                        make_float2(acc[mt][nt][0], acc[mt][nt][1]);
                if (r1 < Mreal)
                    *reinterpret_cast<float2*>(Cb + (size_t)r1 * ldc + cc) =
                        make_float2(acc[mt][nt][2], acc[mt][nt][3]);
            }
        }
    }
}

// ============ fused depthwise 3x3 + qk planes + normsq + v planes ==========
// Block (24,16): 192x16 stripe, 8 outputs per thread along x.
#define DW_TX 24
#define DW_TY 16
__global__ void __launch_bounds__(DW_TX*DW_TY) dwconv_fused(
    const float* __restrict__ in, const float* __restrict__ wdw,
    bf16* __restrict__ qh, bf16* __restrict__ ql,
    bf16* __restrict__ kh, bf16* __restrict__ kl,
    bf16* __restrict__ vh, bf16* __restrict__ vl,
    float* __restrict__ normsq)
{
    const int bc = blockIdx.y;           // b*C3 + o
    const int b  = bc / C3;
    const int o  = bc % C3;
    const float* ip = in + (size_t)bc * HW;

    float w[9];
#pragma unroll
    for (int i = 0; i < 9; i++) w[i] = __ldg(wdw + o * 9 + i);

    const int y  = blockIdx.x * DW_TY + threadIdx.y;
    const int x0 = threadIdx.x * 8;

    float a[8];
#pragma unroll
    for (int i = 0; i < 8; i++) a[i] = 0.f;

#pragma unroll
    for (int dy = 0; dy < 3; dy++) {
        int yy = y + dy - 1;
        if (yy < 0 || yy >= HH) continue;
        const float* rp = ip + (size_t)yy * WW;
        float4 c0 = *reinterpret_cast<const float4*>(rp + x0);
        float4 c1 = *reinterpret_cast<const float4*>(rp + x0 + 4);
        float lft = (x0 > 0)       ? rp[x0 - 1] : 0.f;
        float rgt = (x0 + 8 < WW)  ? rp[x0 + 8] : 0.f;
        float w0 = w[dy*3], w1 = w[dy*3+1], w2 = w[dy*3+2];
        a[0] += w0*lft  + w1*c0.x + w2*c0.y;
        a[1] += w0*c0.x + w1*c0.y + w2*c0.z;
        a[2] += w0*c0.y + w1*c0.z + w2*c0.w;
        a[3] += w0*c0.z + w1*c0.w + w2*c1.x;
        a[4] += w0*c0.w + w1*c1.x + w2*c1.y;
        a[5] += w0*c1.x + w1*c1.y + w2*c1.z;
        a[6] += w0*c1.y + w1*c1.z + w2*c1.w;
        a[7] += w0*c1.z + w1*c1.w + w2*rgt;
    }

    // hi/lo split of the 8 outputs
    uint32_t hv[4], lv[4];
#pragma unroll
    for (int i = 0; i < 4; i++) {
        bf16 hA = __float2bfloat16(a[2*i]);
        bf16 hB = __float2bfloat16(a[2*i+1]);
        bf16 lA = __float2bfloat16(a[2*i]   - __bfloat162float(hA));
        bf16 lB = __float2bfloat16(a[2*i+1] - __bfloat162float(hB));
        __nv_bfloat162 hp(hA, hB), lp2(lA, lB);
        hv[i] = *reinterpret_cast<uint32_t*>(&hp);
        lv[i] = *reinterpret_cast<uint32_t*>(&lp2);
    }

    const int t = o / C0;                // 0=q, 1=k, 2=v
    const int c = o % C0;
    size_t off = ((size_t)b * C0 + c) * HW + (size_t)y * WW + x0;
    bf16* hp;
    bf16* lp;
    if (t == 0)      { hp = qh; lp = ql; }
    else if (t == 1) { hp = kh; lp = kl; }
    else             { hp = vh; lp = vl; }
    *reinterpret_cast<uint4*>(hp + off) = make_uint4(hv[0], hv[1], hv[2], hv[3]);
    *reinterpret_cast<uint4*>(lp + off) = make_uint4(lv[0], lv[1], lv[2], lv[3]);

    if (t < 2) {
        float s = 0.f;
#pragma unroll
        for (int i = 0; i < 8; i++) s += a[i] * a[i];
#pragma unroll
        for (int offm = 16; offm > 0; offm >>= 1)
            s += __shfl_xor_sync(0xffffffffu, s, offm);
        int lane = (threadIdx.y * DW_TX + threadIdx.x) & 31;
        if (lane == 0)
            atomicAdd(&normsq[(b * 2 + t) * C0 + c], s);
    }
}

// ---------------- zero attn + normsq ---------------------------------------
__global__ void zero_small(float* __restrict__ attn, float* __restrict__ normsq)
{
    int i = blockIdx.x * 256 + threadIdx.x;
    if (i < BATCH * NH * HD * HD) attn[i] = 0.f;
    if (i < BATCH * 2 * C0) normsq[i] = 0.f;
}

// ---------------- tensor-core q·k^T ----------------------------------------
#define AT_NSPL 18
#define AT_KBLK (HW/AT_NSPL)   // 2048
#define AT_SK 128
#define AT_SUB (AT_KBLK/AT_SK) // 16
#define AT_SROW 136
#define AT_PLANE (48*AT_SROW*2)
#define AT_STAGE (4*AT_PLANE)
#define AT_SMEM (2*AT_STAGE)

__global__ void __launch_bounds__(256) attn_mma(
    const bf16* __restrict__ qh, const bf16* __restrict__ ql,
    const bf16* __restrict__ kh, const bf16* __restrict__ kl,
    float* __restrict__ attn)
{
    extern __shared__ char smem[];
    const uint32_t sb = smem_u32(smem);
    const int tid  = threadIdx.x;
    const int wid  = tid >> 5;
    const int lane = tid & 31;

    const int bh = blockIdx.y;
    const int b = bh / NH, h = bh % NH;
    const size_t rowbase = ((size_t)b * C0 + h * HD) * HW;
    const bf16* pl[4] = { qh + rowbase, ql + rowbase, kh + rowbase, kl + rowbase };
    const size_t kblk0 = (size_t)blockIdx.x * AT_KBLK;

    float acc[3][6][4];
#pragma unroll
    for (int i = 0; i < 3; i++)
#pragma unroll
        for (int j = 0; j < 6; j++)
#pragma unroll
            for (int q = 0; q < 4; q++) acc[i][j][q] = 0.f;

    auto fill = [&](int sub, int stg) {
        uint32_t base = sb + stg * AT_STAGE;
        size_t k0 = kblk0 + (size_t)sub * AT_SK;
#pragma unroll
        for (int p = 0; p < 4; p++) {
#pragma unroll
            for (int r = 0; r < 3; r++) {
                int cc = tid + r * 256;
                int row = cc >> 4, seg = cc & 15;
                cpa16(base + p * AT_PLANE + (uint32_t)(row * AT_SROW + seg * 8) * 2,
                      pl[p] + (size_t)row * HW + k0 + seg * 8, 16);
            }
        }
        CP_COMMIT();
    };

    fill(0, 0);

    const int kofs = wid * 16;
    const int a_r = lane & 15;
    const int a_c = kofs + (lane >> 4) * 8;
    const int b_r = (lane & 7) + ((lane >> 4) & 1) * 8;
    const int b_c = kofs + ((lane >> 3) & 1) * 8;

    for (int sub = 0; sub < AT_SUB; sub++) {
        CP_WAIT(0);
        __syncthreads();
        if (sub < AT_SUB - 1) fill(sub + 1, (sub + 1) & 1);

        uint32_t base = sb + (sub & 1) * AT_STAGE;
        uint32_t qhf[3][4], qlf[3][4], khf[3][4], klf[3][4];
#pragma unroll
        for (int mt = 0; mt < 3; mt++) {
            uint32_t ao = (uint32_t)((mt * 16 + a_r) * AT_SROW + a_c) * 2;
            ldsm4(base + 0 * AT_PLANE + ao, qhf[mt]);
            ldsm4(base + 1 * AT_PLANE + ao, qlf[mt]);
        }
#pragma unroll
        for (int nt2 = 0; nt2 < 3; nt2++) {
            uint32_t bo = (uint32_t)((nt2 * 16 + b_r) * AT_SROW + b_c) * 2;
            ldsm4(base + 2 * AT_PLANE + bo, khf[nt2]);
            ldsm4(base + 3 * AT_PLANE + bo, klf[nt2]);
        }
#pragma unroll
        for (int mt = 0; mt < 3; mt++)
#pragma unroll
            for (int nt = 0; nt < 6; nt++) {
                const uint32_t* bfh = &khf[nt >> 1][(nt & 1) * 2];
                const uint32_t* bfl = &klf[nt >> 1][(nt & 1) * 2];
                mma16816(acc[mt][nt], qhf[mt], bfh);
                mma16816(acc[mt][nt], qhf[mt], bfl);
                mma16816(acc[mt][nt], qlf[mt], bfh);
            }
        __syncthreads();
    }

    float* red = reinterpret_cast<float*>(smem);   // [48][49]
    for (int i = tid; i < 48 * 49; i += 256) red[i] = 0.f;
    __syncthreads();
    const int erow = lane >> 2;
    const int ecol = (lane & 3) * 2;
#pragma unroll
    for (int mt = 0; mt < 3; mt++) {
        int r0 = mt * 16 + erow;
#pragma unroll
        for (int nt = 0; nt < 6; nt++) {
            int cc = nt * 8 + ecol;
            atomicAdd(&red[r0 * 49 + cc],       acc[mt][nt][0]);
            atomicAdd(&red[r0 * 49 + cc + 1],   acc[mt][nt][1]);
            atomicAdd(&red[(r0 + 8) * 49 + cc],     acc[mt][nt][2]);
            atomicAdd(&red[(r0 + 8) * 49 + cc + 1], acc[mt][nt][3]);
        }
    }
    __syncthreads();
    float* ap = attn + (size_t)bh * HD * HD;
    for (int i = tid; i < HD * HD; i += 256) {
        int r = i / HD, cl = i % HD;
        atomicAdd(&ap[i], red[r * 49 + cl]);
    }
}

// ---------------- scale by norms + temperature, softmax over e -------------
__global__ void softmax_attn(float* __restrict__ attn, const float* __restrict__ normsq,
                             const float* __restrict__ logtemp)
{
    const int bh = blockIdx.x;
    const int b = bh / NH, h = bh % NH;
    const int d = threadIdx.x;
    if (d >= HD) return;

    float lt = logtemp[h];
    float temp = (lt > 20.f ? lt : log1pf(expf(lt))) + 1e-6f;

    const float* nq = normsq + (b * 2 + 0) * C0 + h * HD;
    const float* nk = normsq + (b * 2 + 1) * C0 + h * HD;
    float* row = attn + ((size_t)bh * HD + d) * HD;
    const float qn = fmaxf(sqrtf(nq[d]), 1e-12f);

    float vals[HD];
    float mx = -1e30f;
#pragma unroll
    for (int e = 0; e < HD; e++) {
        float kn = fmaxf(sqrtf(nk[e]), 1e-12f);
        float v = row[e] / (qn * kn) * temp;
        vals[e] = v;
        mx = fmaxf(mx, v);
    }
    float s = 0.f;
#pragma unroll
    for (int e = 0; e < HD; e++) {
        vals[e] = expf(vals[e] - mx);
        s += vals[e];
    }
    float inv = 1.f / s;
#pragma unroll
    for (int e = 0; e < HD; e++) row[e] = vals[e] * inv;
}

// ---------------- W2[b] = w_proj @ blockdiag(attn[b]) -> bf16 hi/lo --------
__global__ void build_w2(const float* __restrict__ wproj, const float* __restrict__ attn,
                         bf16* __restrict__ w2h, bf16* __restrict__ w2l)
{
    int idx = blockIdx.x * 256 + threadIdx.x;
    if (idx >= BATCH * C0 * C0) return;
    int cc = idx % C0;
    int o  = (idx / C0) % C0;
    int b  = idx / (C0 * C0);
    int h = cc / HD, e = cc % HD;
    float s = 0.f;
#pragma unroll
    for (int d = 0; d < HD; d++)
        s += wproj[o * C0 + h * HD + d] * attn[(((size_t)b * NH + h) * HD + d) * HD + e];
    bf16 hi = __float2bfloat16(s);
    bf16 lo = __float2bfloat16(s - __bfloat162float(hi));
    w2h[idx] = hi;
    w2l[idx] = lo;
}

// ---------------- launcher -------------------------------------------------
extern "C" void kernel_launch(void* const* d_in, const int* in_sizes, int n_in,
                              void* d_out, int out_size)
{
    const float* x      = (const float*)d_in[0];
    const float* w_qkv  = (const float*)d_in[1];
    const float* w_dw   = (const float*)d_in[2];
    const float* w_proj = (const float*)d_in[3];
    const float* ltemp  = (const float*)d_in[4];
    float* out = (float*)d_out;

    float *qkv1, *normsq, *attn;
    bf16 *xh, *xl, *vh, *vl, *qh, *ql, *kh, *kl, *wqh, *wql, *w2h, *w2l;
    cudaGetSymbolAddress((void**)&qkv1, g_qkv1);
    cudaGetSymbolAddress((void**)&normsq, g_normsq);
    cudaGetSymbolAddress((void**)&attn, g_attn);
    cudaGetSymbolAddress((void**)&xh,  g_xh);
    cudaGetSymbolAddress((void**)&xl,  g_xl);
    cudaGetSymbolAddress((void**)&vh,  g_vh);
    cudaGetSymbolAddress((void**)&vl,  g_vl);
    cudaGetSymbolAddress((void**)&qh,  g_qh);
    cudaGetSymbolAddress((void**)&ql,  g_ql);
    cudaGetSymbolAddress((void**)&kh,  g_kh);
    cudaGetSymbolAddress((void**)&kl,  g_kl);
    cudaGetSymbolAddress((void**)&wqh, g_wqh);
    cudaGetSymbolAddress((void**)&wql, g_wql);
    cudaGetSymbolAddress((void**)&w2h, g_w2h);
    cudaGetSymbolAddress((void**)&w2l, g_w2l);

    cudaFuncSetAttribute(gemm_mma, cudaFuncAttributeMaxDynamicSharedMemorySize, SMEM_B);
    cudaFuncSetAttribute(attn_mma, cudaFuncAttributeMaxDynamicSharedMemorySize, AT_SMEM);

    // 0) split x and w_qkv to bf16 hi/lo planes; zero accumulators
    {
        int total = BATCH * C0 * HW;
        split_batched<<<total / 4 / 256, 256>>>(x, (size_t)C0 * HW, C0 * HW, xh, xl, total);
        int wtot = C3 * C0;
        split_batched<<<(wtot / 4 + 255) / 256, 256>>>(w_qkv, wtot, wtot, wqh, wql, wtot);
        zero_small<<<(BATCH * NH * HD * HD + 255) / 256, 256>>>(attn, normsq);
    }
    // 1) qkv1 = w_qkv @ x
    {
        dim3 grid(HW / BN, (C3 + BM - 1) / BM, BATCH);
        gemm_mma<<<grid, 256, SMEM_B>>>(wqh, wql, xh, xl, qkv1,
                                        C3, HW, 0, (size_t)C0 * HW, (size_t)C3 * HW);
    }
    // 2) fused depthwise 3x3 -> q,k,v hi/lo planes + qk normsq
    {
        dim3 grid(HH / DW_TY, BATCH * C3);
        dwconv_fused<<<grid, dim3(DW_TX, DW_TY)>>>(qkv1, w_dw, qh, ql, kh, kl,
                                                   vh, vl, normsq);
    }
    // 3) tensor-core q.k^T
    {
        dim3 grid(AT_NSPL, BATCH * NH);
        attn_mma<<<grid, 256, AT_SMEM>>>(qh, ql, kh, kl, attn);
    }
    // 4) softmax
    softmax_attn<<<BATCH * NH, 64>>>(attn, normsq, ltemp);
    // 5) W2
    build_w2<<<(BATCH * C0 * C0 + 255) / 256, 256>>>(w_proj, attn, w2h, w2l);
    // 6) out = W2 @ v
    {
        dim3 grid(HW / BN, (C0 + BM - 1) / BM, BATCH);
        gemm_mma<<<grid, 256, SMEM_B>>>(w2h, w2l, vh, vl, out,
                                        C0, HW, (size_t)C0 * C0, (size_t)C0 * HW,
                                        (size_t)C0 * HW);
    }
}

// round 9
// speedup vs baseline: 3.8199x; 1.2000x over previous
#include <cuda_runtime.h>
#include <cuda_fp16.h>
#include <math.h>
#include <cstdint>

#define BATCH 2
#define C0 192
#define HH 192
#define WW 192
#define HW (HH*WW)          // 36864
#define C3 (3*C0)           // 576
#define NH 4
#define HD 48
#define KDIM 192

typedef __half fp16;

// ---------------- scratch (device globals; no allocs allowed) --------------
__device__ float g_qkv1[BATCH*C3*HW];      // after 1x1 conv
__device__ float g_normsq[BATCH*2*C0];     // [b][q|k][c]  sum of squares
__device__ float g_attn[BATCH*NH*HD*HD];   // raw dots -> softmaxed attn
__device__ fp16  g_x16[BATCH*C0*HW];       // x single fp16 plane
__device__ fp16  g_v16[BATCH*C0*HW];       // v single fp16 plane
__device__ fp16  g_k16[BATCH*C0*HW];       // k single fp16 plane
__device__ fp16  g_qh[BATCH*C0*HW];        // q hi plane
__device__ fp16  g_ql[BATCH*C0*HW];        // q lo plane
__device__ fp16  g_wqh[C3*C0];             // w_qkv hi
__device__ fp16  g_wql[C3*C0];             // w_qkv lo
__device__ fp16  g_w2h[BATCH*C0*C0];       // w2 hi
__device__ fp16  g_w2l[BATCH*C0*C0];       // w2 lo

// ======================= small helpers =====================================
__device__ __forceinline__ uint32_t smem_u32(const void* p) {
    uint32_t a;
    asm("{ .reg .u64 t; cvta.to.shared.u64 t, %1; cvt.u32.u64 %0, t; }"
        : "=r"(a) : "l"(p));
    return a;
}
__device__ __forceinline__ void ldsm4(uint32_t addr, uint32_t* r) {
    asm volatile("ldmatrix.sync.aligned.m8n8.x4.shared.b16 {%0,%1,%2,%3}, [%4];"
        : "=r"(r[0]), "=r"(r[1]), "=r"(r[2]), "=r"(r[3]) : "r"(addr));
}
__device__ __forceinline__ void ldsm4t(uint32_t addr, uint32_t* r) {
    asm volatile("ldmatrix.sync.aligned.m8n8.x4.trans.shared.b16 {%0,%1,%2,%3}, [%4];"
        : "=r"(r[0]), "=r"(r[1]), "=r"(r[2]), "=r"(r[3]) : "r"(addr));
}
__device__ __forceinline__ void mma16816(float* d, const uint32_t* a, const uint32_t* b) {
    asm volatile(
        "mma.sync.aligned.m16n8k16.row.col.f32.f16.f16.f32 "
        "{%0,%1,%2,%3}, {%4,%5,%6,%7}, {%8,%9}, {%0,%1,%2,%3};"
        : "+f"(d[0]), "+f"(d[1]), "+f"(d[2]), "+f"(d[3])
        : "r"(a[0]), "r"(a[1]), "r"(a[2]), "r"(a[3]), "r"(b[0]), "r"(b[1]));
}
__device__ __forceinline__ void cpa16(uint32_t dst, const void* src, int bytes) {
    asm volatile("cp.async.cg.shared.global [%0], [%1], 16, %2;"
        :: "r"(dst), "l"(src), "r"(bytes));
}
#define CP_COMMIT() asm volatile("cp.async.commit_group;")
#define CP_WAIT(n)  asm volatile("cp.async.wait_group %0;" :: "n"(n))

__device__ __forceinline__ uint32_t pack2h(float a, float b) {
    __half2 p = __halves2half2(__float2half_rn(a), __float2half_rn(b));
    return *reinterpret_cast<uint32_t*>(&p);
}

// ======================= conversion kernels ================================
// fp32 -> single fp16 plane, contiguous, 8 elems/thread
__global__ void __launch_bounds__(256) cvt_f16(
    const float* __restrict__ src, fp16* __restrict__ dst, int total)
{
    int i8 = (blockIdx.x * 256 + threadIdx.x) * 8;
    if (i8 >= total) return;
    float4 v0 = *reinterpret_cast<const float4*>(src + i8);
    float4 v1 = *reinterpret_cast<const float4*>(src + i8 + 4);
    uint4 o;
    o.x = pack2h(v0.x, v0.y); o.y = pack2h(v0.z, v0.w);
    o.z = pack2h(v1.x, v1.y); o.w = pack2h(v1.z, v1.w);
    *reinterpret_cast<uint4*>(dst + i8) = o;
}

// fp32 -> fp16 hi/lo planes, contiguous, 4 elems/thread
__global__ void __launch_bounds__(256) split_f16(
    const float* __restrict__ src, fp16* __restrict__ h, fp16* __restrict__ l, int total)
{
    int i4 = (blockIdx.x * 256 + threadIdx.x) * 4;
    if (i4 >= total) return;
    float4 v = *reinterpret_cast<const float4*>(src + i4);
    fp16 h0 = __float2half_rn(v.x), h1 = __float2half_rn(v.y);
    fp16 h2 = __float2half_rn(v.z), h3 = __float2half_rn(v.w);
    float l0 = v.x - __half2float(h0), l1 = v.y - __half2float(h1);
    float l2 = v.z - __half2float(h2), l3 = v.w - __half2float(h3);
    uint2 ho, lo;
    ho.x = pack2h(__half2float(h0), __half2float(h1));
    ho.y = pack2h(__half2float(h2), __half2float(h3));
    lo.x = pack2h(l0, l1); lo.y = pack2h(l2, l3);
    *reinterpret_cast<uint2*>(h + i4) = ho;
    *reinterpret_cast<uint2*>(l + i4) = lo;
}

// ======================= tensor-core GEMM (2-pass fp16 split) ==============
// C[M,N] = (Ah+Al)[M,192] @ B[192,N]; A fp16 hi/lo, B single fp16.
#define BM 128
#define BN 128
#define BK 32
#define NCHUNK (KDIM/BK)     // 6
#define SA 40
#define SB 136
#define A_PLANE_B (BM*SA*2)                  // 10240
#define B_PLANE_B (BK*SB*2)                  // 8704
#define OFF_AH 0
#define OFF_AL (A_PLANE_B)
#define OFF_B  (2*A_PLANE_B)
#define BUF_B  (2*A_PLANE_B + B_PLANE_B)     // 29184
#define NSTAGE 3
#define SMEM_B (NSTAGE*BUF_B)                // 87552

__global__ void __launch_bounds__(256) gemm_mma(
    const fp16* __restrict__ Ah, const fp16* __restrict__ Al,
    const fp16* __restrict__ B,
    float* __restrict__ C, int Mreal, int ldc,
    size_t sAb, size_t sBb, size_t sCb)
{
    extern __shared__ char smem[];
    const uint32_t sb = smem_u32(smem);
    const int tid  = threadIdx.x;
    const int wid  = tid >> 5;
    const int lane = tid & 31;
    const int warp_m = wid & 1;
    const int warp_n = wid >> 1;

    const int bz = blockIdx.z;
    const fp16* Ahb = Ah + bz * sAb;
    const fp16* Alb = Al + bz * sAb;
    const fp16* Bb  = B  + bz * sBb;
    float*      Cb  = C  + bz * sCb;

    const int m0 = blockIdx.y * BM;
    const int n0 = blockIdx.x * BN;
    const bool mactive = (m0 + warp_m * 64) < Mreal;

    float acc[4][4][4];
#pragma unroll
    for (int i = 0; i < 4; i++)
#pragma unroll
        for (int j = 0; j < 4; j++)
#pragma unroll
            for (int q = 0; q < 4; q++) acc[i][j][q] = 0.f;

    auto issue = [&](int kc, int buf) {
        uint32_t base = sb + buf * BUF_B;
        // A: 512 16B-chunks per plane, 2 per thread per plane
#pragma unroll
        for (int r = 0; r < 2; r++) {
            int c = tid * 2 + r;
            int row = c >> 2, seg = c & 3;
            int grow = m0 + row;
            int ok = (grow < Mreal) ? 16 : 0;
            int gr = (grow < Mreal) ? grow : 0;
            size_t go = (size_t)gr * KDIM + kc + seg * 8;
            uint32_t so = (uint32_t)(row * SA + seg * 8) * 2;
            cpa16(base + OFF_AH + so, Ahb + go, ok);
            cpa16(base + OFF_AL + so, Alb + go, ok);
        }
        // B: 512 16B-chunks, 2 per thread
#pragma unroll
        for (int r = 0; r < 2; r++) {
            int c = tid * 2 + r;
            int row = c >> 4, seg = c & 15;
            size_t go = (size_t)(kc + row) * HW + n0 + seg * 8;
            uint32_t so = (uint32_t)(row * SB + seg * 8) * 2;
            cpa16(base + OFF_B + so, Bb + go, 16);
        }
        CP_COMMIT();
    };

    issue(0, 0);
    issue(BK, 1);

    const int arow = warp_m * 64 + (lane & 15);
    const int acolb = (lane >> 4) * 8;
    const int brow = (lane & 7) + ((lane >> 3) & 1) * 8;
    const int bcol = warp_n * 32 + ((lane >> 4) & 1) * 8;

    int buf = 0;
    for (int ch = 0; ch < NCHUNK; ch++) {
        if (ch < NCHUNK - 1) { CP_WAIT(1); } else { CP_WAIT(0); }
        __syncthreads();
        if (ch < NCHUNK - 2) {
            int nb = buf + 2; if (nb >= NSTAGE) nb -= NSTAGE;
            issue((ch + 2) * BK, nb);
        }

        if (mactive) {
            uint32_t base = sb + buf * BUF_B;
#pragma unroll
            for (int ks = 0; ks < 2; ks++) {
                uint32_t ah[4][4], al[4][4], bh[2][4];
                int acol = ks * 16 + acolb;
#pragma unroll
                for (int mt = 0; mt < 4; mt++) {
                    uint32_t ao = (uint32_t)((arow + mt * 16) * SA + acol) * 2;
                    ldsm4(base + OFF_AH + ao, ah[mt]);
                    ldsm4(base + OFF_AL + ao, al[mt]);
                }
                int krow = ks * 16 + brow;
#pragma unroll
                for (int p = 0; p < 2; p++) {
                    uint32_t bo = (uint32_t)(krow * SB + bcol + p * 16) * 2;
                    ldsm4t(base + OFF_B + bo, bh[p]);
                }
#pragma unroll
                for (int mt = 0; mt < 4; mt++)
#pragma unroll
                    for (int nt = 0; nt < 4; nt++) {
                        const uint32_t* bf = &bh[nt >> 1][(nt & 1) * 2];
                        mma16816(acc[mt][nt], ah[mt], bf);
                        mma16816(acc[mt][nt], al[mt], bf);
                    }
            }
        }
        buf++; if (buf >= NSTAGE) buf = 0;
    }

    const int erow = lane >> 2;
    const int ecol = (lane & 3) * 2;
    if (mactive) {
#pragma unroll
        for (int mt = 0; mt < 4; mt++) {
            int r0 = m0 + warp_m * 64 + mt * 16 + erow;
            int r1 = r0 + 8;
#pragma unroll
            for (int nt = 0; nt < 4; nt++) {
                int cc = n0 + warp_n * 32 + nt * 8 + ecol;
                if (r0 < Mreal)
                    *reinterpret_cast<float2*>(Cb + (size_t)r0 * ldc + cc) =
                        make_float2(acc[mt][nt][0], acc[mt][nt][1]);
                if (r1 < Mreal)
                    *reinterpret_cast<float2*>(Cb + (size_t)r1 * ldc + cc) =
                        make_float2(acc[mt][nt][2], acc[mt][nt][3]);
            }
        }
    }
}

// ============ fused depthwise 3x3 + qk/v fp16 planes + normsq ==============
#define DW_TX 24
#define DW_TY 16
__global__ void __launch_bounds__(DW_TX*DW_TY) dwconv_fused(
    const float* __restrict__ in, const float* __restrict__ wdw,
    fp16* __restrict__ qh, fp16* __restrict__ ql,
    fp16* __restrict__ k16, fp16* __restrict__ v16,
    float* __restrict__ normsq)
{
    const int bc = blockIdx.y;           // b*C3 + o
    const int b  = bc / C3;
    const int o  = bc % C3;
    const float* ip = in + (size_t)bc * HW;

    float w[9];
#pragma unroll
    for (int i = 0; i < 9; i++) w[i] = __ldg(wdw + o * 9 + i);

    const int y  = blockIdx.x * DW_TY + threadIdx.y;
    const int x0 = threadIdx.x * 8;

    float a[8];
#pragma unroll
    for (int i = 0; i < 8; i++) a[i] = 0.f;

#pragma unroll
    for (int dy = 0; dy < 3; dy++) {
        int yy = y + dy - 1;
        if (yy < 0 || yy >= HH) continue;
        const float* rp = ip + (size_t)yy * WW;
        float4 c0 = *reinterpret_cast<const float4*>(rp + x0);
        float4 c1 = *reinterpret_cast<const float4*>(rp + x0 + 4);
        float lft = (x0 > 0)       ? rp[x0 - 1] : 0.f;
        float rgt = (x0 + 8 < WW)  ? rp[x0 + 8] : 0.f;
        float w0 = w[dy*3], w1 = w[dy*3+1], w2 = w[dy*3+2];
        a[0] += w0*lft  + w1*c0.x + w2*c0.y;
        a[1] += w0*c0.x + w1*c0.y + w2*c0.z;
        a[2] += w0*c0.y + w1*c0.z + w2*c0.w;
        a[3] += w0*c0.z + w1*c0.w + w2*c1.x;
        a[4] += w0*c0.w + w1*c1.x + w2*c1.y;
        a[5] += w0*c1.x + w1*c1.y + w2*c1.z;
        a[6] += w0*c1.y + w1*c1.z + w2*c1.w;
        a[7] += w0*c1.z + w1*c1.w + w2*rgt;
    }

    const int t = o / C0;                // 0=q, 1=k, 2=v
    const int c = o % C0;
    size_t off = ((size_t)b * C0 + c) * HW + (size_t)y * WW + x0;

    // hi plane values (all branches)
    uint4 hv;
    hv.x = pack2h(a[0], a[1]); hv.y = pack2h(a[2], a[3]);
    hv.z = pack2h(a[4], a[5]); hv.w = pack2h(a[6], a[7]);

    if (t == 0) {
        // q: hi/lo fp16 planes
        float lo[8];
#pragma unroll
        for (int i = 0; i < 8; i++)
            lo[i] = a[i] - __half2float(__float2half_rn(a[i]));
        uint4 lv;
        lv.x = pack2h(lo[0], lo[1]); lv.y = pack2h(lo[2], lo[3]);
        lv.z = pack2h(lo[4], lo[5]); lv.w = pack2h(lo[6], lo[7]);
        *reinterpret_cast<uint4*>(qh + off) = hv;
        *reinterpret_cast<uint4*>(ql + off) = lv;
    } else if (t == 1) {
        *reinterpret_cast<uint4*>(k16 + off) = hv;
    } else {
        *reinterpret_cast<uint4*>(v16 + off) = hv;
    }

    if (t < 2) {
        float s = 0.f;
#pragma unroll
        for (int i = 0; i < 8; i++) s += a[i] * a[i];
#pragma unroll
        for (int offm = 16; offm > 0; offm >>= 1)
            s += __shfl_xor_sync(0xffffffffu, s, offm);
        int lane = (threadIdx.y * DW_TX + threadIdx.x) & 31;
        if (lane == 0)
            atomicAdd(&normsq[(b * 2 + t) * C0 + c], s);
    }
}

// ---------------- zero attn + normsq ---------------------------------------
__global__ void zero_small(float* __restrict__ attn, float* __restrict__ normsq)
{
    int i = blockIdx.x * 256 + threadIdx.x;
    if (i < BATCH * NH * HD * HD) attn[i] = 0.f;
    if (i < BATCH * 2 * C0) normsq[i] = 0.f;
}

// ---------------- tensor-core q·k^T (2-pass fp16) --------------------------
#define AT_NSPL 18
#define AT_KBLK (HW/AT_NSPL)   // 2048
#define AT_SK 128
#define AT_SUB (AT_KBLK/AT_SK) // 16
#define AT_SROW 136
#define AT_PLANE (48*AT_SROW*2)    // 13056
#define AT_STAGE (3*AT_PLANE)      // 39168
#define AT_SMEM (2*AT_STAGE)       // 78336

__global__ void __launch_bounds__(256) attn_mma(
    const fp16* __restrict__ qh, const fp16* __restrict__ ql,
    const fp16* __restrict__ k16,
    float* __restrict__ attn)
{
    extern __shared__ char smem[];
    const uint32_t sb = smem_u32(smem);
    const int tid  = threadIdx.x;
    const int wid  = tid >> 5;
    const int lane = tid & 31;

    const int bh = blockIdx.y;
    const int b = bh / NH, h = bh % NH;
    const size_t rowbase = ((size_t)b * C0 + h * HD) * HW;
    const fp16* pl[3] = { qh + rowbase, ql + rowbase, k16 + rowbase };
    const size_t kblk0 = (size_t)blockIdx.x * AT_KBLK;

    float acc[3][6][4];
#pragma unroll
    for (int i = 0; i < 3; i++)
#pragma unroll
        for (int j = 0; j < 6; j++)
#pragma unroll
            for (int q = 0; q < 4; q++) acc[i][j][q] = 0.f;

    auto fill = [&](int sub, int stg) {
        uint32_t base = sb + stg * AT_STAGE;
        size_t k0 = kblk0 + (size_t)sub * AT_SK;
#pragma unroll
        for (int p = 0; p < 3; p++) {
#pragma unroll
            for (int r = 0; r < 3; r++) {
                int cc = tid + r * 256;
                int row = cc >> 4, seg = cc & 15;
                cpa16(base + p * AT_PLANE + (uint32_t)(row * AT_SROW + seg * 8) * 2,
                      pl[p] + (size_t)row * HW + k0 + seg * 8, 16);
            }
        }
        CP_COMMIT();
    };

    fill(0, 0);

    const int kofs = wid * 16;
    const int a_r = lane & 15;
    const int a_c = kofs + (lane >> 4) * 8;
    const int b_r = (lane & 7) + ((lane >> 4) & 1) * 8;
    const int b_c = kofs + ((lane >> 3) & 1) * 8;

    for (int sub = 0; sub < AT_SUB; sub++) {
        CP_WAIT(0);
        __syncthreads();
        if (sub < AT_SUB - 1) fill(sub + 1, (sub + 1) & 1);

        uint32_t base = sb + (sub & 1) * AT_STAGE;
        uint32_t qhf[3][4], qlf[3][4], kf[3][4];
#pragma unroll
        for (int mt = 0; mt < 3; mt++) {
            uint32_t ao = (uint32_t)((mt * 16 + a_r) * AT_SROW + a_c) * 2;
            ldsm4(base + 0 * AT_PLANE + ao, qhf[mt]);
            ldsm4(base + 1 * AT_PLANE + ao, qlf[mt]);
        }
#pragma unroll
        for (int nt2 = 0; nt2 < 3; nt2++) {
            uint32_t bo = (uint32_t)((nt2 * 16 + b_r) * AT_SROW + b_c) * 2;
            ldsm4(base + 2 * AT_PLANE + bo, kf[nt2]);
        }
#pragma unroll
        for (int mt = 0; mt < 3; mt++)
#pragma unroll
            for (int nt = 0; nt < 6; nt++) {
                const uint32_t* bf = &kf[nt >> 1][(nt & 1) * 2];
                mma16816(acc[mt][nt], qhf[mt], bf);
                mma16816(acc[mt][nt], qlf[mt], bf);
            }
        __syncthreads();
    }

    float* red = reinterpret_cast<float*>(smem);   // [48][49]
    for (int i = tid; i < 48 * 49; i += 256) red[i] = 0.f;
    __syncthreads();
    const int erow = lane >> 2;
    const int ecol = (lane & 3) * 2;
#pragma unroll
    for (int mt = 0; mt < 3; mt++) {
        int r0 = mt * 16 + erow;
#pragma unroll
        for (int nt = 0; nt < 6; nt++) {
            int cc = nt * 8 + ecol;
            atomicAdd(&red[r0 * 49 + cc],       acc[mt][nt][0]);
            atomicAdd(&red[r0 * 49 + cc + 1],   acc[mt][nt][1]);
            atomicAdd(&red[(r0 + 8) * 49 + cc],     acc[mt][nt][2]);
            atomicAdd(&red[(r0 + 8) * 49 + cc + 1], acc[mt][nt][3]);
        }
    }
    __syncthreads();
    float* ap = attn + (size_t)bh * HD * HD;
    for (int i = tid; i < HD * HD; i += 256) {
        int r = i / HD, cl = i % HD;
        atomicAdd(&ap[i], red[r * 49 + cl]);
    }
}

// ---------------- scale by norms + temperature, softmax over e -------------
__global__ void softmax_attn(float* __restrict__ attn, const float* __restrict__ normsq,
                             const float* __restrict__ logtemp)
{
    const int bh = blockIdx.x;
    const int b = bh / NH, h = bh % NH;
    const int d = threadIdx.x;
    if (d >= HD) return;

    float lt = logtemp[h];
    float temp = (lt > 20.f ? lt : log1pf(expf(lt))) + 1e-6f;

    const float* nq = normsq + (b * 2 + 0) * C0 + h * HD;
    const float* nk = normsq + (b * 2 + 1) * C0 + h * HD;
    float* row = attn + ((size_t)bh * HD + d) * HD;
    const float qn = fmaxf(sqrtf(nq[d]), 1e-12f);

    float vals[HD];
    float mx = -1e30f;
#pragma unroll
    for (int e = 0; e < HD; e++) {
        float kn = fmaxf(sqrtf(nk[e]), 1e-12f);
        float v = row[e] / (qn * kn) * temp;
        vals[e] = v;
        mx = fmaxf(mx, v);
    }
    float s = 0.f;
#pragma unroll
    for (int e = 0; e < HD; e++) {
        vals[e] = expf(vals[e] - mx);
        s += vals[e];
    }
    float inv = 1.f / s;
#pragma unroll
    for (int e = 0; e < HD; e++) row[e] = vals[e] * inv;
}

// ---------------- W2[b] = w_proj @ blockdiag(attn[b]) -> fp16 hi/lo --------
__global__ void build_w2(const float* __restrict__ wproj, const float* __restrict__ attn,
                         fp16* __restrict__ w2h, fp16* __restrict__ w2l)
{
    int idx = blockIdx.x * 256 + threadIdx.x;
    if (idx >= BATCH * C0 * C0) return;
    int cc = idx % C0;
    int o  = (idx / C0) % C0;
    int b  = idx / (C0 * C0);
    int h = cc / HD, e = cc % HD;
    float s = 0.f;
#pragma unroll
    for (int d = 0; d < HD; d++)
        s += wproj[o * C0 + h * HD + d] * attn[(((size_t)b * NH + h) * HD + d) * HD + e];
    fp16 hi = __float2half_rn(s);
    fp16 lo = __float2half_rn(s - __half2float(hi));
    w2h[idx] = hi;
    w2l[idx] = lo;
}

// ---------------- launcher -------------------------------------------------
extern "C" void kernel_launch(void* const* d_in, const int* in_sizes, int n_in,
                              void* d_out, int out_size)
{
    const float* x      = (const float*)d_in[0];
    const float* w_qkv  = (const float*)d_in[1];
    const float* w_dw   = (const float*)d_in[2];
    const float* w_proj = (const float*)d_in[3];
    const float* ltemp  = (const float*)d_in[4];
    float* out = (float*)d_out;

    float *qkv1, *normsq, *attn;
    fp16 *x16, *v16, *k16, *qh, *ql, *wqh, *wql, *w2h, *w2l;
    cudaGetSymbolAddress((void**)&qkv1, g_qkv1);
    cudaGetSymbolAddress((void**)&normsq, g_normsq);
    cudaGetSymbolAddress((void**)&attn, g_attn);
    cudaGetSymbolAddress((void**)&x16, g_x16);
    cudaGetSymbolAddress((void**)&v16, g_v16);
    cudaGetSymbolAddress((void**)&k16, g_k16);
    cudaGetSymbolAddress((void**)&qh,  g_qh);
    cudaGetSymbolAddress((void**)&ql,  g_ql);
    cudaGetSymbolAddress((void**)&wqh, g_wqh);
    cudaGetSymbolAddress((void**)&wql, g_wql);
    cudaGetSymbolAddress((void**)&w2h, g_w2h);
    cudaGetSymbolAddress((void**)&w2l, g_w2l);

    cudaFuncSetAttribute(gemm_mma, cudaFuncAttributeMaxDynamicSharedMemorySize, SMEM_B);
    cudaFuncSetAttribute(attn_mma, cudaFuncAttributeMaxDynamicSharedMemorySize, AT_SMEM);

    // 0) convert x -> single fp16; split w_qkv -> hi/lo; zero accumulators
    {
        int total = BATCH * C0 * HW;
        cvt_f16<<<total / 8 / 256, 256>>>(x, x16, total);
        int wtot = C3 * C0;
        split_f16<<<(wtot / 4 + 255) / 256, 256>>>(w_qkv, wqh, wql, wtot);
        zero_small<<<(BATCH * NH * HD * HD + 255) / 256, 256>>>(attn, normsq);
    }
    // 1) qkv1 = w_qkv @ x  (2-pass fp16 split)
    {
        dim3 grid(HW / BN, (C3 + BM - 1) / BM, BATCH);
        gemm_mma<<<grid, 256, SMEM_B>>>(wqh, wql, x16, qkv1,
                                        C3, HW, 0, (size_t)C0 * HW, (size_t)C3 * HW);
    }
    // 2) fused depthwise 3x3 -> q hi/lo, k, v fp16 planes + qk normsq
    {
        dim3 grid(HH / DW_TY, BATCH * C3);
        dwconv_fused<<<grid, dim3(DW_TX, DW_TY)>>>(qkv1, w_dw, qh, ql, k16, v16, normsq);
    }
    // 3) tensor-core q.k^T (2-pass)
    {
        dim3 grid(AT_NSPL, BATCH * NH);
        attn_mma<<<grid, 256, AT_SMEM>>>(qh, ql, k16, attn);
    }
    // 4) softmax
    softmax_attn<<<BATCH * NH, 64>>>(attn, normsq, ltemp);
    // 5) W2 -> fp16 hi/lo
    build_w2<<<(BATCH * C0 * C0 + 255) / 256, 256>>>(w_proj, attn, w2h, w2l);
    // 6) out = W2 @ v  (2-pass fp16 split)
    {
        dim3 grid(HW / BN, (C0 + BM - 1) / BM, BATCH);
        gemm_mma<<<grid, 256, SMEM_B>>>(w2h, w2l, v16, out,
                                        C0, HW, (size_t)C0 * C0, (size_t)C0 * HW,
                                        (size_t)C0 * HW);
    }
}

// round 10
// speedup vs baseline: 3.8917x; 1.0188x over previous
#include <cuda_runtime.h>
#include <cuda_fp16.h>
#include <math.h>
#include <cstdint>

#define BATCH 2
#define C0 192
#define HH 192
#define WW 192
#define HW (HH*WW)          // 36864
#define C3 (3*C0)           // 576
#define NH 4
#define HD 48
#define KDIM 192

typedef __half fp16;

// ---------------- scratch (device globals; no allocs allowed) --------------
__device__ fp16  g_qkv1[BATCH*C3*HW];      // after 1x1 conv (fp16)
__device__ float g_normsq[BATCH*2*C0];     // [b][q|k][c]  sum of squares
__device__ float g_attn[BATCH*NH*HD*HD];   // raw dots -> softmaxed attn
__device__ fp16  g_x16[BATCH*C0*HW];       // x single fp16 plane
__device__ fp16  g_v16[BATCH*C0*HW];       // v single fp16 plane
__device__ fp16  g_k16[BATCH*C0*HW];       // k single fp16 plane
__device__ fp16  g_qh[BATCH*C0*HW];        // q hi plane
__device__ fp16  g_ql[BATCH*C0*HW];        // q lo plane
__device__ fp16  g_wqh[C3*C0];             // w_qkv hi
__device__ fp16  g_wql[C3*C0];             // w_qkv lo
__device__ fp16  g_w2h[BATCH*C0*C0];       // w2 hi
__device__ fp16  g_w2l[BATCH*C0*C0];       // w2 lo

// ======================= small helpers =====================================
__device__ __forceinline__ uint32_t smem_u32(const void* p) {
    uint32_t a;
    asm("{ .reg .u64 t; cvta.to.shared.u64 t, %1; cvt.u32.u64 %0, t; }"
        : "=r"(a) : "l"(p));
    return a;
}
__device__ __forceinline__ void ldsm4(uint32_t addr, uint32_t* r) {
    asm volatile("ldmatrix.sync.aligned.m8n8.x4.shared.b16 {%0,%1,%2,%3}, [%4];"
        : "=r"(r[0]), "=r"(r[1]), "=r"(r[2]), "=r"(r[3]) : "r"(addr));
}
__device__ __forceinline__ void ldsm4t(uint32_t addr, uint32_t* r) {
    asm volatile("ldmatrix.sync.aligned.m8n8.x4.trans.shared.b16 {%0,%1,%2,%3}, [%4];"
        : "=r"(r[0]), "=r"(r[1]), "=r"(r[2]), "=r"(r[3]) : "r"(addr));
}
__device__ __forceinline__ void mma16816(float* d, const uint32_t* a, const uint32_t* b) {
    asm volatile(
        "mma.sync.aligned.m16n8k16.row.col.f32.f16.f16.f32 "
        "{%0,%1,%2,%3}, {%4,%5,%6,%7}, {%8,%9}, {%0,%1,%2,%3};"
        : "+f"(d[0]), "+f"(d[1]), "+f"(d[2]), "+f"(d[3])
        : "r"(a[0]), "r"(a[1]), "r"(a[2]), "r"(a[3]), "r"(b[0]), "r"(b[1]));
}
__device__ __forceinline__ void cpa16(uint32_t dst, const void* src, int bytes) {
    asm volatile("cp.async.cg.shared.global [%0], [%1], 16, %2;"
        :: "r"(dst), "l"(src), "r"(bytes));
}
#define CP_COMMIT() asm volatile("cp.async.commit_group;")
#define CP_WAIT(n)  asm volatile("cp.async.wait_group %0;" :: "n"(n))

__device__ __forceinline__ uint32_t pack2h(float a, float b) {
    __half2 p = __halves2half2(__float2half_rn(a), __float2half_rn(b));
    return *reinterpret_cast<uint32_t*>(&p);
}

// ======================= conversion kernels ================================
__global__ void __launch_bounds__(256) cvt_f16(
    const float* __restrict__ src, fp16* __restrict__ dst, int total)
{
    int i8 = (blockIdx.x * 256 + threadIdx.x) * 8;
    if (i8 >= total) return;
    float4 v0 = *reinterpret_cast<const float4*>(src + i8);
    float4 v1 = *reinterpret_cast<const float4*>(src + i8 + 4);
    uint4 o;
    o.x = pack2h(v0.x, v0.y); o.y = pack2h(v0.z, v0.w);
    o.z = pack2h(v1.x, v1.y); o.w = pack2h(v1.z, v1.w);
    *reinterpret_cast<uint4*>(dst + i8) = o;
}

__global__ void __launch_bounds__(256) split_f16(
    const float* __restrict__ src, fp16* __restrict__ h, fp16* __restrict__ l, int total)
{
    int i4 = (blockIdx.x * 256 + threadIdx.x) * 4;
    if (i4 >= total) return;
    float4 v = *reinterpret_cast<const float4*>(src + i4);
    fp16 h0 = __float2half_rn(v.x), h1 = __float2half_rn(v.y);
    fp16 h2 = __float2half_rn(v.z), h3 = __float2half_rn(v.w);
    float l0 = v.x - __half2float(h0), l1 = v.y - __half2float(h1);
    float l2 = v.z - __half2float(h2), l3 = v.w - __half2float(h3);
    uint2 ho, lo;
    ho.x = pack2h(__half2float(h0), __half2float(h1));
    ho.y = pack2h(__half2float(h2), __half2float(h3));
    lo.x = pack2h(l0, l1); lo.y = pack2h(l2, l3);
    *reinterpret_cast<uint2*>(h + i4) = ho;
    *reinterpret_cast<uint2*>(l + i4) = lo;
}

// ======================= tensor-core GEMM (2-pass fp16 split) ==============
// Warp layout 4m x 2n (A-dup 2x, B-dup 4x). HALF_OUT selects fp16/fp32 C.
#define BM 128
#define BN 128
#define BK 32
#define NCHUNK (KDIM/BK)     // 6
#define SA 40
#define SB 136
#define A_PLANE_B (BM*SA*2)                  // 10240
#define B_PLANE_B (BK*SB*2)                  // 8704
#define OFF_AH 0
#define OFF_AL (A_PLANE_B)
#define OFF_B  (2*A_PLANE_B)
#define BUF_B  (2*A_PLANE_B + B_PLANE_B)     // 29184
#define NSTAGE 3
#define SMEM_B (NSTAGE*BUF_B)                // 87552

template<bool HALF_OUT>
__global__ void __launch_bounds__(256) gemm_mma(
    const fp16* __restrict__ Ah, const fp16* __restrict__ Al,
    const fp16* __restrict__ B,
    void* __restrict__ Cv, int Mreal, int ldc,
    size_t sAb, size_t sBb, size_t sCb)
{
    extern __shared__ char smem[];
    const uint32_t sb = smem_u32(smem);
    const int tid  = threadIdx.x;
    const int wid  = tid >> 5;
    const int lane = tid & 31;
    const int warp_m = wid & 3;      // 4 m-groups of 32 rows
    const int warp_n = wid >> 2;     // 2 n-groups of 64 cols

    const int bz = blockIdx.z;
    const fp16* Ahb = Ah + bz * sAb;
    const fp16* Alb = Al + bz * sAb;
    const fp16* Bb  = B  + bz * sBb;

    const int m0 = blockIdx.y * BM;
    const int n0 = blockIdx.x * BN;
    const bool mactive = (m0 + warp_m * 32) < Mreal;

    float acc[2][8][4];
#pragma unroll
    for (int i = 0; i < 2; i++)
#pragma unroll
        for (int j = 0; j < 8; j++)
#pragma unroll
            for (int q = 0; q < 4; q++) acc[i][j][q] = 0.f;

    auto issue = [&](int kc, int buf) {
        uint32_t base = sb + buf * BUF_B;
#pragma unroll
        for (int r = 0; r < 2; r++) {
            int c = tid * 2 + r;
            int row = c >> 2, seg = c & 3;
            int grow = m0 + row;
            int ok = (grow < Mreal) ? 16 : 0;
            int gr = (grow < Mreal) ? grow : 0;
            size_t go = (size_t)gr * KDIM + kc + seg * 8;
            uint32_t so = (uint32_t)(row * SA + seg * 8) * 2;
            cpa16(base + OFF_AH + so, Ahb + go, ok);
            cpa16(base + OFF_AL + so, Alb + go, ok);
        }
#pragma unroll
        for (int r = 0; r < 2; r++) {
            int c = tid * 2 + r;
            int row = c >> 4, seg = c & 15;
            size_t go = (size_t)(kc + row) * HW + n0 + seg * 8;
            uint32_t so = (uint32_t)(row * SB + seg * 8) * 2;
            cpa16(base + OFF_B + so, Bb + go, 16);
        }
        CP_COMMIT();
    };

    issue(0, 0);
    issue(BK, 1);

    const int arow = warp_m * 32 + (lane & 15);
    const int acolb = (lane >> 4) * 8;
    const int brow = (lane & 7) + ((lane >> 3) & 1) * 8;
    const int bcolb = warp_n * 64 + ((lane >> 4) & 1) * 8;

    int buf = 0;
    for (int ch = 0; ch < NCHUNK; ch++) {
        if (ch < NCHUNK - 1) { CP_WAIT(1); } else { CP_WAIT(0); }
        __syncthreads();
        if (ch < NCHUNK - 2) {
            int nb = buf + 2; if (nb >= NSTAGE) nb -= NSTAGE;
            issue((ch + 2) * BK, nb);
        }

        if (mactive) {
            uint32_t base = sb + buf * BUF_B;
#pragma unroll
            for (int ks = 0; ks < 2; ks++) {
                uint32_t ah[2][4], al[2][4], bh[4][4];
                int acol = ks * 16 + acolb;
#pragma unroll
                for (int mt = 0; mt < 2; mt++) {
                    uint32_t ao = (uint32_t)((arow + mt * 16) * SA + acol) * 2;
                    ldsm4(base + OFF_AH + ao, ah[mt]);
                    ldsm4(base + OFF_AL + ao, al[mt]);
                }
                int krow = ks * 16 + brow;
#pragma unroll
                for (int p = 0; p < 4; p++) {
                    uint32_t bo = (uint32_t)(krow * SB + bcolb + p * 16) * 2;
                    ldsm4t(base + OFF_B + bo, bh[p]);
                }
#pragma unroll
                for (int mt = 0; mt < 2; mt++)
#pragma unroll
                    for (int nt = 0; nt < 8; nt++) {
                        const uint32_t* bf = &bh[nt >> 1][(nt & 1) * 2];
                        mma16816(acc[mt][nt], ah[mt], bf);
                        mma16816(acc[mt][nt], al[mt], bf);
                    }
            }
        }
        buf++; if (buf >= NSTAGE) buf = 0;
    }

    const int erow = lane >> 2;
    const int ecol = (lane & 3) * 2;
    if (mactive) {
#pragma unroll
        for (int mt = 0; mt < 2; mt++) {
            int r0 = m0 + warp_m * 32 + mt * 16 + erow;
            int r1 = r0 + 8;
#pragma unroll
            for (int nt = 0; nt < 8; nt++) {
                int cc = n0 + warp_n * 64 + nt * 8 + ecol;
                if (HALF_OUT) {
                    fp16* Cb = (fp16*)Cv + bz * sCb;
                    if (r0 < Mreal)
                        *reinterpret_cast<uint32_t*>(Cb + (size_t)r0 * ldc + cc) =
                            pack2h(acc[mt][nt][0], acc[mt][nt][1]);
                    if (r1 < Mreal)
                        *reinterpret_cast<uint32_t*>(Cb + (size_t)r1 * ldc + cc) =
                            pack2h(acc[mt][nt][2], acc[mt][nt][3]);
                } else {
                    float* Cb = (float*)Cv + bz * sCb;
                    if (r0 < Mreal)
                        *reinterpret_cast<float2*>(Cb + (size_t)r0 * ldc + cc) =
                            make_float2(acc[mt][nt][0], acc[mt][nt][1]);
                    if (r1 < Mreal)
                        *reinterpret_cast<float2*>(Cb + (size_t)r1 * ldc + cc) =
                            make_float2(acc[mt][nt][2], acc[mt][nt][3]);
                }
            }
        }
    }
}

// ============ fused depthwise 3x3 (fp16 in) + qk/v fp16 planes + normsq ====
#define DW_TX 24
#define DW_TY 16
__global__ void __launch_bounds__(DW_TX*DW_TY) dwconv_fused(
    const fp16* __restrict__ in, const float* __restrict__ wdw,
    fp16* __restrict__ qh, fp16* __restrict__ ql,
    fp16* __restrict__ k16, fp16* __restrict__ v16,
    float* __restrict__ normsq)
{
    const int bc = blockIdx.y;           // b*C3 + o
    const int b  = bc / C3;
    const int o  = bc % C3;
    const fp16* ip = in + (size_t)bc * HW;

    float w[9];
#pragma unroll
    for (int i = 0; i < 9; i++) w[i] = __ldg(wdw + o * 9 + i);

    const int y  = blockIdx.x * DW_TY + threadIdx.y;
    const int x0 = threadIdx.x * 8;

    float a[8];
#pragma unroll
    for (int i = 0; i < 8; i++) a[i] = 0.f;

#pragma unroll
    for (int dy = 0; dy < 3; dy++) {
        int yy = y + dy - 1;
        if (yy < 0 || yy >= HH) continue;
        const fp16* rp = ip + (size_t)yy * WW;
        uint4 raw = *reinterpret_cast<const uint4*>(rp + x0);
        const __half2* hh = reinterpret_cast<const __half2*>(&raw);
        float c[8];
#pragma unroll
        for (int j = 0; j < 4; j++) {
            float2 f = __half22float2(hh[j]);
            c[2*j] = f.x; c[2*j+1] = f.y;
        }
        float lft = (x0 > 0)       ? __half2float(rp[x0 - 1]) : 0.f;
        float rgt = (x0 + 8 < WW)  ? __half2float(rp[x0 + 8]) : 0.f;
        float w0 = w[dy*3], w1 = w[dy*3+1], w2 = w[dy*3+2];
        a[0] += w0*lft  + w1*c[0] + w2*c[1];
        a[1] += w0*c[0] + w1*c[1] + w2*c[2];
        a[2] += w0*c[1] + w1*c[2] + w2*c[3];
        a[3] += w0*c[2] + w1*c[3] + w2*c[4];
        a[4] += w0*c[3] + w1*c[4] + w2*c[5];
        a[5] += w0*c[4] + w1*c[5] + w2*c[6];
        a[6] += w0*c[5] + w1*c[6] + w2*c[7];
        a[7] += w0*c[6] + w1*c[7] + w2*rgt;
    }

    const int t = o / C0;                // 0=q, 1=k, 2=v
    const int c = o % C0;
    size_t off = ((size_t)b * C0 + c) * HW + (size_t)y * WW + x0;

    uint4 hv;
    hv.x = pack2h(a[0], a[1]); hv.y = pack2h(a[2], a[3]);
    hv.z = pack2h(a[4], a[5]); hv.w = pack2h(a[6], a[7]);

    if (t == 0) {
        float lo[8];
#pragma unroll
        for (int i = 0; i < 8; i++)
            lo[i] = a[i] - __half2float(__float2half_rn(a[i]));
        uint4 lv;
        lv.x = pack2h(lo[0], lo[1]); lv.y = pack2h(lo[2], lo[3]);
        lv.z = pack2h(lo[4], lo[5]); lv.w = pack2h(lo[6], lo[7]);
        *reinterpret_cast<uint4*>(qh + off) = hv;
        *reinterpret_cast<uint4*>(ql + off) = lv;
    } else if (t == 1) {
        *reinterpret_cast<uint4*>(k16 + off) = hv;
    } else {
        *reinterpret_cast<uint4*>(v16 + off) = hv;
    }

    if (t < 2) {
        float s = 0.f;
#pragma unroll
        for (int i = 0; i < 8; i++) s += a[i] * a[i];
#pragma unroll
        for (int offm = 16; offm > 0; offm >>= 1)
            s += __shfl_xor_sync(0xffffffffu, s, offm);
        int lane = (threadIdx.y * DW_TX + threadIdx.x) & 31;
        if (lane == 0)
            atomicAdd(&normsq[(b * 2 + t) * C0 + c], s);
    }
}

// ---------------- zero attn + normsq ---------------------------------------
__global__ void zero_small(float* __restrict__ attn, float* __restrict__ normsq)
{
    int i = blockIdx.x * 256 + threadIdx.x;
    if (i < BATCH * NH * HD * HD) attn[i] = 0.f;
    if (i < BATCH * 2 * C0) normsq[i] = 0.f;
}

// ---------------- tensor-core q·k^T (2-pass fp16) --------------------------
#define AT_NSPL 18
#define AT_KBLK (HW/AT_NSPL)   // 2048
#define AT_SK 128
#define AT_SUB (AT_KBLK/AT_SK) // 16
#define AT_SROW 136
#define AT_PLANE (48*AT_SROW*2)    // 13056
#define AT_STAGE (3*AT_PLANE)      // 39168
#define AT_SMEM (2*AT_STAGE)       // 78336

__global__ void __launch_bounds__(256) attn_mma(
    const fp16* __restrict__ qh, const fp16* __restrict__ ql,
    const fp16* __restrict__ k16,
    float* __restrict__ attn)
{
    extern __shared__ char smem[];
    const uint32_t sb = smem_u32(smem);
    const int tid  = threadIdx.x;
    const int wid  = tid >> 5;
    const int lane = tid & 31;

    const int bh = blockIdx.y;
    const int b = bh / NH, h = bh % NH;
    const size_t rowbase = ((size_t)b * C0 + h * HD) * HW;
    const fp16* pl[3] = { qh + rowbase, ql + rowbase, k16 + rowbase };
    const size_t kblk0 = (size_t)blockIdx.x * AT_KBLK;

    float acc[3][6][4];
#pragma unroll
    for (int i = 0; i < 3; i++)
#pragma unroll
        for (int j = 0; j < 6; j++)
#pragma unroll
            for (int q = 0; q < 4; q++) acc[i][j][q] = 0.f;

    auto fill = [&](int sub, int stg) {
        uint32_t base = sb + stg * AT_STAGE;
        size_t k0 = kblk0 + (size_t)sub * AT_SK;
#pragma unroll
        for (int p = 0; p < 3; p++) {
#pragma unroll
            for (int r = 0; r < 3; r++) {
                int cc = tid + r * 256;
                int row = cc >> 4, seg = cc & 15;
                cpa16(base + p * AT_PLANE + (uint32_t)(row * AT_SROW + seg * 8) * 2,
                      pl[p] + (size_t)row * HW + k0 + seg * 8, 16);
            }
        }
        CP_COMMIT();
    };

    fill(0, 0);

    const int kofs = wid * 16;
    const int a_r = lane & 15;
    const int a_c = kofs + (lane >> 4) * 8;
    const int b_r = (lane & 7) + ((lane >> 4) & 1) * 8;
    const int b_c = kofs + ((lane >> 3) & 1) * 8;

    for (int sub = 0; sub < AT_SUB; sub++) {
        CP_WAIT(0);
        __syncthreads();
        if (sub < AT_SUB - 1) fill(sub + 1, (sub + 1) & 1);

        uint32_t base = sb + (sub & 1) * AT_STAGE;
        uint32_t qhf[3][4], qlf[3][4], kf[3][4];
#pragma unroll
        for (int mt = 0; mt < 3; mt++) {
            uint32_t ao = (uint32_t)((mt * 16 + a_r) * AT_SROW + a_c) * 2;
            ldsm4(base + 0 * AT_PLANE + ao, qhf[mt]);
            ldsm4(base + 1 * AT_PLANE + ao, qlf[mt]);
        }
#pragma unroll
        for (int nt2 = 0; nt2 < 3; nt2++) {
            uint32_t bo = (uint32_t)((nt2 * 16 + b_r) * AT_SROW + b_c) * 2;
            ldsm4(base + 2 * AT_PLANE + bo, kf[nt2]);
        }
#pragma unroll
        for (int mt = 0; mt < 3; mt++)
#pragma unroll
            for (int nt = 0; nt < 6; nt++) {
                const uint32_t* bf = &kf[nt >> 1][(nt & 1) * 2];
                mma16816(acc[mt][nt], qhf[mt], bf);
                mma16816(acc[mt][nt], qlf[mt], bf);
            }
        __syncthreads();
    }

    float* red = reinterpret_cast<float*>(smem);   // [48][49]
    for (int i = tid; i < 48 * 49; i += 256) red[i] = 0.f;
    __syncthreads();
    const int erow = lane >> 2;
    const int ecol = (lane & 3) * 2;
#pragma unroll
    for (int mt = 0; mt < 3; mt++) {
        int r0 = mt * 16 + erow;
#pragma unroll
        for (int nt = 0; nt < 6; nt++) {
            int cc = nt * 8 + ecol;
            atomicAdd(&red[r0 * 49 + cc],       acc[mt][nt][0]);
            atomicAdd(&red[r0 * 49 + cc + 1],   acc[mt][nt][1]);
            atomicAdd(&red[(r0 + 8) * 49 + cc],     acc[mt][nt][2]);
            atomicAdd(&red[(r0 + 8) * 49 + cc + 1], acc[mt][nt][3]);
        }
    }
    __syncthreads();
    float* ap = attn + (size_t)bh * HD * HD;
    for (int i = tid; i < HD * HD; i += 256) {
        int r = i / HD, cl = i % HD;
        atomicAdd(&ap[i], red[r * 49 + cl]);
    }
}

// ---------------- scale by norms + temperature, softmax over e -------------
__global__ void softmax_attn(float* __restrict__ attn, const float* __restrict__ normsq,
                             const float* __restrict__ logtemp)
{
    const int bh = blockIdx.x;
    const int b = bh / NH, h = bh % NH;
    const int d = threadIdx.x;
    if (d >= HD) return;

    float lt = logtemp[h];
    float temp = (lt > 20.f ? lt : log1pf(expf(lt))) + 1e-6f;

    const float* nq = normsq + (b * 2 + 0) * C0 + h * HD;
    const float* nk = normsq + (b * 2 + 1) * C0 + h * HD;
    float* row = attn + ((size_t)bh * HD + d) * HD;
    const float qn = fmaxf(sqrtf(nq[d]), 1e-12f);

    float vals[HD];
    float mx = -1e30f;
#pragma unroll
    for (int e = 0; e < HD; e++) {
        float kn = fmaxf(sqrtf(nk[e]), 1e-12f);
        float v = row[e] / (qn * kn) * temp;
        vals[e] = v;
        mx = fmaxf(mx, v);
    }
    float s = 0.f;
#pragma unroll
    for (int e = 0; e < HD; e++) {
        vals[e] = expf(vals[e] - mx);
        s += vals[e];
    }
    float inv = 1.f / s;
#pragma unroll
    for (int e = 0; e < HD; e++) row[e] = vals[e] * inv;
}

// ---------------- W2[b] = w_proj @ blockdiag(attn[b]) -> fp16 hi/lo --------
__global__ void build_w2(const float* __restrict__ wproj, const float* __restrict__ attn,
                         fp16* __restrict__ w2h, fp16* __restrict__ w2l)
{
    int idx = blockIdx.x * 256 + threadIdx.x;
    if (idx >= BATCH * C0 * C0) return;
    int cc = idx % C0;
    int o  = (idx / C0) % C0;
    int b  = idx / (C0 * C0);
    int h = cc / HD, e = cc % HD;
    float s = 0.f;
#pragma unroll
    for (int d = 0; d < HD; d++)
        s += wproj[o * C0 + h * HD + d] * attn[(((size_t)b * NH + h) * HD + d) * HD + e];
    fp16 hi = __float2half_rn(s);
    fp16 lo = __float2half_rn(s - __half2float(hi));
    w2h[idx] = hi;
    w2l[idx] = lo;
}

// ---------------- launcher -------------------------------------------------
extern "C" void kernel_launch(void* const* d_in, const int* in_sizes, int n_in,
                              void* d_out, int out_size)
{
    const float* x      = (const float*)d_in[0];
    const float* w_qkv  = (const float*)d_in[1];
    const float* w_dw   = (const float*)d_in[2];
    const float* w_proj = (const float*)d_in[3];
    const float* ltemp  = (const float*)d_in[4];
    float* out = (float*)d_out;

    float *normsq, *attn;
    fp16 *qkv1, *x16, *v16, *k16, *qh, *ql, *wqh, *wql, *w2h, *w2l;
    cudaGetSymbolAddress((void**)&qkv1, g_qkv1);
    cudaGetSymbolAddress((void**)&normsq, g_normsq);
    cudaGetSymbolAddress((void**)&attn, g_attn);
    cudaGetSymbolAddress((void**)&x16, g_x16);
    cudaGetSymbolAddress((void**)&v16, g_v16);
    cudaGetSymbolAddress((void**)&k16, g_k16);
    cudaGetSymbolAddress((void**)&qh,  g_qh);
    cudaGetSymbolAddress((void**)&ql,  g_ql);
    cudaGetSymbolAddress((void**)&wqh, g_wqh);
    cudaGetSymbolAddress((void**)&wql, g_wql);
    cudaGetSymbolAddress((void**)&w2h, g_w2h);
    cudaGetSymbolAddress((void**)&w2l, g_w2l);

    cudaFuncSetAttribute(gemm_mma<true>,  cudaFuncAttributeMaxDynamicSharedMemorySize, SMEM_B);
    cudaFuncSetAttribute(gemm_mma<false>, cudaFuncAttributeMaxDynamicSharedMemorySize, SMEM_B);
    cudaFuncSetAttribute(attn_mma, cudaFuncAttributeMaxDynamicSharedMemorySize, AT_SMEM);

    // 0) convert x -> fp16; split w_qkv -> hi/lo; zero accumulators
    {
        int total = BATCH * C0 * HW;
        cvt_f16<<<total / 8 / 256, 256>>>(x, x16, total);
        int wtot = C3 * C0;
        split_f16<<<(wtot / 4 + 255) / 256, 256>>>(w_qkv, wqh, wql, wtot);
        zero_small<<<(BATCH * NH * HD * HD + 255) / 256, 256>>>(attn, normsq);
    }
    // 1) qkv1 = w_qkv @ x  (fp16 output)
    {
        dim3 grid(HW / BN, (C3 + BM - 1) / BM, BATCH);
        gemm_mma<true><<<grid, 256, SMEM_B>>>(wqh, wql, x16, qkv1,
                                              C3, HW, 0, (size_t)C0 * HW,
                                              (size_t)C3 * HW);
    }
    // 2) fused depthwise 3x3 (fp16 in) -> q hi/lo, k, v fp16 planes + normsq
    {
        dim3 grid(HH / DW_TY, BATCH * C3);
        dwconv_fused<<<grid, dim3(DW_TX, DW_TY)>>>(qkv1, w_dw, qh, ql, k16, v16, normsq);
    }
    // 3) tensor-core q.k^T (2-pass)
    {
        dim3 grid(AT_NSPL, BATCH * NH);
        attn_mma<<<grid, 256, AT_SMEM>>>(qh, ql, k16, attn);
    }
    // 4) softmax
    softmax_attn<<<BATCH * NH, 64>>>(attn, normsq, ltemp);
    // 5) W2 -> fp16 hi/lo
    build_w2<<<(BATCH * C0 * C0 + 255) / 256, 256>>>(w_proj, attn, w2h, w2l);
    // 6) out = W2 @ v  (fp32 output)
    {
        dim3 grid(HW / BN, (C0 + BM - 1) / BM, BATCH);
        gemm_mma<false><<<grid, 256, SMEM_B>>>(w2h, w2l, v16, out,
                                               C0, HW, (size_t)C0 * C0,
                                               (size_t)C0 * HW, (size_t)C0 * HW);
    }
}